// round 11
// baseline (speedup 1.0000x reference)
#include <cuda_runtime.h>
#include <cuda_fp16.h>
#include <math.h>
#include <stdint.h>

#define N_NODES 10000
#define E_EDGES 160000
#define IN_F    128
#define H1_F    512
#define H2_F    1024
#define H3_F    512
#define OUT_F   32

// Weight-transpose buffer offsets (fp16 elements)
#define W1T_OFF 0
#define W2T_OFF (IN_F * H1_F)
#define W3T_OFF (W2T_OFF + H1_F * H2_F)
#define W4T_OFF (W3T_OFF + H2_F * H3_F)
#define WT_TOTAL (W4T_OFF + H3_F * OUT_F)

// ===========================================================================
// Scratch (static device globals)
// ===========================================================================
__device__ int   g_is64;
__device__ float g_dinv[N_NODES];
__device__ int   g_cnt[N_NODES];
__device__ int   g_cursor[N_NODES];
__device__ int   g_rowptr[N_NODES + 1];
__device__ int   g_col[E_EDGES];
__device__ float4 g_buf0[(size_t)N_NODES * OUT_F / 4];  // fp32 L4 lin
__device__ uint4 g_A[(size_t)N_NODES * H2_F * 2 / 16];  // fp16 activations A
__device__ uint4 g_A2[(size_t)N_NODES * H1_F * 2 / 16]; // fp16 activations B
__device__ uint4 g_Bh[(WT_TOTAL * 2 + 15) / 16];        // fp16 weights (T)

// ===========================================================================
// helpers
// ===========================================================================
__device__ __forceinline__ uint32_t smem_to_u32(const void* p) {
    uint32_t a;
    asm("{ .reg .u64 t; cvta.to.shared.u64 t, %1; cvt.u32.u64 %0, t; }"
        : "=r"(a) : "l"(p));
    return a;
}
__device__ __forceinline__ void cp_async16(uint32_t s, const void* g) {
    asm volatile("cp.async.cg.shared.global [%0], [%1], 16;"
                 :: "r"(s), "l"(__cvta_generic_to_global(g)) : "memory");
}
__device__ __forceinline__ void cp_commit() {
    asm volatile("cp.async.commit_group;" ::: "memory");
}
template <int NN>
__device__ __forceinline__ void cp_wait() {
    asm volatile("cp.async.wait_group %0;" :: "n"(NN) : "memory");
}
__device__ __forceinline__ void mma16816(float* c, const uint32_t* a,
                                         const uint32_t* b) {
    asm volatile(
        "mma.sync.aligned.m16n8k16.row.col.f32.f16.f16.f32 "
        "{%0,%1,%2,%3}, {%4,%5,%6,%7}, {%8,%9}, {%0,%1,%2,%3};"
        : "+f"(c[0]), "+f"(c[1]), "+f"(c[2]), "+f"(c[3])
        : "r"(a[0]), "r"(a[1]), "r"(a[2]), "r"(a[3]), "r"(b[0]), "r"(b[1]));
}
__device__ __forceinline__ void load_edge(const void* ei, int e, int E,
                                          int& s, int& d) {
    if (g_is64) {
        const long long* p = (const long long*)ei;
        s = (int)p[e]; d = (int)p[e + E];
    } else {
        const int* p = (const int*)ei;
        s = p[e]; d = p[e + E];
    }
}

// ===========================================================================
// Setup: zero counters + dtype detect + all-weight transpose, one kernel.
// Blocks 0..39: zero/detect.  Blocks 40..1143: W1..W4 transpose to fp16 [N,K].
// ===========================================================================
__global__ __launch_bounds__(256)
void k_setup(const void* __restrict__ ei,
             const float* __restrict__ W1, const float* __restrict__ W2,
             const float* __restrict__ W3, const float* __restrict__ W4,
             __half* __restrict__ hi) {
    const int tx = threadIdx.x, ty = threadIdx.y;   // (32, 8)
    const int tid = ty * 32 + tx;
    int b = blockIdx.x;
    if (b < 40) {
        int i = b * 256 + tid;
        if (i < N_NODES) { g_cnt[i] = 0; g_cursor[i] = 0; }
        if (b == 0) {
            if (tid == 0) g_is64 = 1;
            __syncthreads();
            if (tid < 128) {
                const long long* p = (const long long*)ei;
                long long v = p[tid];
                if (v < 0 || v >= N_NODES) atomicAnd(&g_is64, 0);
            }
        }
        return;
    }
    b -= 40;
    const float* W; int K, N; size_t off;
    if (b < 64)        { W = W1; K = IN_F; N = H1_F; off = W1T_OFF; }
    else if (b < 576)  { b -= 64;   W = W2; K = H1_F; N = H2_F; off = W2T_OFF; }
    else if (b < 1088) { b -= 576;  W = W3; K = H2_F; N = H3_F; off = W3T_OFF; }
    else               { b -= 1088; W = W4; K = H3_F; N = OUT_F; off = W4T_OFF; }
    int KT = K / 32;
    int k0 = (b % KT) * 32, n0 = (b / KT) * 32;

    __shared__ float t[32][33];
#pragma unroll
    for (int j = 0; j < 4; j++)
        t[ty + j * 8][tx] = W[(size_t)(k0 + ty + j * 8) * N + (n0 + tx)];
    __syncthreads();
#pragma unroll
    for (int j = 0; j < 4; j++) {
        float v = t[tx][ty + j * 8];
        int n = n0 + ty + j * 8;
        int k = k0 + tx;
        hi[off + (size_t)n * K + k] = __float2half_rn(v);
    }
}

// ===========================================================================
// CSR chain
// ===========================================================================
__global__ void k_count(const void* __restrict__ ei, int E) {
    int e = blockIdx.x * blockDim.x + threadIdx.x;
    if (e >= E) return;
    int s, d;
    load_edge(ei, e, E, s, d);
    atomicAdd(&g_cnt[d], 1);
}
__global__ __launch_bounds__(1024)
void k_scan_dinv() {
    __shared__ int wsum[32];
    __shared__ int s_off;
    const int tid = threadIdx.x;
    const int lane = tid & 31;
    const int wid = tid >> 5;
    if (tid == 0) s_off = 0;
    __syncthreads();
    for (int base = 0; base < N_NODES; base += 1024) {
        int i = base + tid;
        int v = (i < N_NODES) ? g_cnt[i] : 0;
        if (i < N_NODES) g_dinv[i] = rsqrtf((float)v + 1.0f);
        int x = v;
#pragma unroll
        for (int o = 1; o < 32; o <<= 1) {
            int t = __shfl_up_sync(0xFFFFFFFFu, x, o);
            if (lane >= o) x += t;
        }
        if (lane == 31) wsum[wid] = x;
        __syncthreads();
        if (wid == 0) {
            int w = wsum[lane];
#pragma unroll
            for (int o = 1; o < 32; o <<= 1) {
                int t = __shfl_up_sync(0xFFFFFFFFu, w, o);
                if (lane >= o) w += t;
            }
            wsum[lane] = w;
        }
        __syncthreads();
        int incl = x + ((wid > 0) ? wsum[wid - 1] : 0);
        int off = s_off;
        if (i < N_NODES) g_rowptr[i + 1] = off + incl;
        __syncthreads();
        if (tid == 1023) s_off = off + incl;
        __syncthreads();
    }
    if (tid == 0) g_rowptr[0] = 0;
}
__global__ void k_fill(const void* __restrict__ ei, int E) {
    int e = blockIdx.x * blockDim.x + threadIdx.x;
    if (e >= E) return;
    int s, d;
    load_edge(ei, e, E, s, d);
    int pos = g_rowptr[d] + atomicAdd(&g_cursor[d], 1);
    g_col[pos] = s;
}

// ===========================================================================
// fp16 1-pass GEMM, 3-stage cp.async pipeline, min 2 CTAs/SM.
// A fp16 [M,K]; B fp16 [N,K] pre-T; fp32 acc. CTA 128x128, 8 warps 4mx2n.
// EPI: 0 bias+relu fp32 | 1 bias+relu fp16 | 2 raw fp16 | 3 raw fp32
// NG:  bounds-guard B rows / C cols against Ncols (for Ncols < 128)
// ===========================================================================
#define KC 32
#define SROW 40                      // fp16 row stride (80 B)
#define TILE_B (128 * SROW * 2)      // 10240 B
#define STAGE_B (2 * TILE_B)         // 20480 B (A, B)
#define GEMM_SMEM (3 * STAGE_B)      // 61440 B

template <int EPI, bool NG>
__global__ __launch_bounds__(256, 2)
void k_gemm_mma(const uint4* __restrict__ A, const __half* __restrict__ B,
                const float* __restrict__ bias, float* __restrict__ C,
                __half2* __restrict__ Oh,
                int M, int K, int Ncols) {
    extern __shared__ char sm[];
    const uint32_t smb = smem_to_u32(sm);
    const int tid = threadIdx.x;
    const int lane = tid & 31;
    const int wid = tid >> 5;
    const int warp_m = wid & 3;
    const int warp_n = wid >> 2;
    const int g = lane >> 2;
    const int tig = lane & 3;
    const int mrow0 = blockIdx.y * 128;
    const int ncol0 = blockIdx.x * 128;
    const int KU = K >> 3;
    const int nChunks = K / KC;

    float acc[2][8][4];
#pragma unroll
    for (int i = 0; i < 2; i++)
#pragma unroll
        for (int j = 0; j < 8; j++)
#pragma unroll
            for (int q = 0; q < 4; q++) acc[i][j][q] = 0.0f;

    auto load_chunk = [&](int it, int st) {
        const int ku0 = it * (KC / 8);
        const uint32_t sb = smb + st * STAGE_B;
#pragma unroll
        for (int q = tid; q < 512; q += 256) {
            int row = q >> 2;
            int cb = q & 3;
            uint32_t so = (uint32_t)(row * 80 + cb * 16);
            int gm = mrow0 + row;
            if (gm < M) {
                cp_async16(sb + so, A + (size_t)gm * KU + ku0 + cb);
            } else {
                *(uint4*)(sm + st * STAGE_B + so) = make_uint4(0, 0, 0, 0);
            }
            int brow = ncol0 + row;
            if (!NG || brow < Ncols) {
                size_t bb = (size_t)brow * K + it * KC + cb * 8;
                cp_async16(sb + TILE_B + so, B + bb);
            } else {
                *(uint4*)(sm + st * STAGE_B + TILE_B + so) = make_uint4(0, 0, 0, 0);
            }
        }
        cp_commit();
    };

    load_chunk(0, 0);
    load_chunk(1, 1);
    for (int it = 0; it < nChunks; it++) {
        const int cur = it % 3;
        if (it + 2 < nChunks) {
            load_chunk(it + 2, (it + 2) % 3);
            cp_wait<2>();
        } else if (it + 1 < nChunks) {
            cp_wait<1>();
        } else {
            cp_wait<0>();
        }
        __syncthreads();

        const __half* sA = (const __half*)(sm + cur * STAGE_B);
        const __half* sB = (const __half*)(sm + cur * STAGE_B + TILE_B);

#pragma unroll
        for (int ks = 0; ks < KC / 16; ks++) {
            const int k0 = ks * 16;
            uint32_t ah[2][4];
#pragma unroll
            for (int mt = 0; mt < 2; mt++) {
                int r0 = warp_m * 32 + mt * 16 + g;
                int c0 = k0 + tig * 2;
                ah[mt][0] = *(const uint32_t*)(sA + r0 * SROW + c0);
                ah[mt][1] = *(const uint32_t*)(sA + (r0 + 8) * SROW + c0);
                ah[mt][2] = *(const uint32_t*)(sA + r0 * SROW + c0 + 8);
                ah[mt][3] = *(const uint32_t*)(sA + (r0 + 8) * SROW + c0 + 8);
            }
            uint32_t bh[8][2];
#pragma unroll
            for (int nt = 0; nt < 8; nt++) {
                int r0 = warp_n * 64 + nt * 8 + g;
                int c0 = k0 + tig * 2;
                bh[nt][0] = *(const uint32_t*)(sB + r0 * SROW + c0);
                bh[nt][1] = *(const uint32_t*)(sB + r0 * SROW + c0 + 8);
            }
#pragma unroll
            for (int mt = 0; mt < 2; mt++)
#pragma unroll
                for (int nt = 0; nt < 8; nt++) mma16816(acc[mt][nt], ah[mt], bh[nt]);
        }
        __syncthreads();
    }

    // Epilogue
#pragma unroll
    for (int mt = 0; mt < 2; mt++) {
        int rbase = mrow0 + warp_m * 32 + mt * 16;
#pragma unroll
        for (int nt = 0; nt < 8; nt++) {
            int col = ncol0 + warp_n * 64 + nt * 8 + tig * 2;
            if (NG && col >= Ncols) continue;
            float b0 = 0.0f, b1 = 0.0f;
            if (EPI == 0 || EPI == 1) { b0 = bias[col]; b1 = bias[col + 1]; }
#pragma unroll
            for (int half = 0; half < 2; half++) {
                int r = rbase + g + half * 8;
                if (r >= M) continue;
                float v0 = acc[mt][nt][half * 2 + 0] + b0;
                float v1 = acc[mt][nt][half * 2 + 1] + b1;
                if (EPI == 0 || EPI == 1) { v0 = fmaxf(v0, 0.0f); v1 = fmaxf(v1, 0.0f); }
                if (EPI == 0 || EPI == 3) {
                    *(float2*)(C + (size_t)r * Ncols + col) = make_float2(v0, v1);
                } else {
                    Oh[((size_t)r * Ncols + col) >> 1] = __floats2half2_rn(v0, v1);
                }
            }
        }
    }
}

// ===========================================================================
// Aggregations (weights rebuilt from g_dinv; g_wt eliminated)
// ===========================================================================
// fp16 in, H=512, block(128) per node.
// OUTMODE 0: fp16 out (no bias) | OUTMODE 2: bias+relu -> fp16 out
template <int OUTMODE>
__global__ __launch_bounds__(128)
void k_agg512_h(const uint2* __restrict__ lin,       // fp16 [N,512] as uint2
                const float* __restrict__ bias,
                __half2* __restrict__ outh) {
    const int node = blockIdx.x;
    const int tid = threadIdx.x;
    float dii = g_dinv[node];
    float w0 = dii * dii;

    uint2 sv = lin[(size_t)node * 128 + tid];
    float2 f01 = __half22float2(*(const __half2*)&sv.x);
    float2 f23 = __half22float2(*(const __half2*)&sv.y);
    float a0 = f01.x * w0, a1 = f01.y * w0, a2 = f23.x * w0, a3 = f23.y * w0;

    __shared__ int   s_col[128];
    __shared__ float s_w[128];
    const int beg = g_rowptr[node];
    const int end = g_rowptr[node + 1];
    for (int j0 = beg; j0 < end; j0 += 128) {
        int n = min(128, end - j0);
        __syncthreads();
        if (tid < n) {
            int c = g_col[j0 + tid];
            s_col[tid] = c;
            s_w[tid] = g_dinv[c] * dii;
        }
        __syncthreads();
        // 1-deep row prefetch
        uint2 v = lin[(size_t)s_col[0] * 128 + tid];
        for (int j = 0; j < n; j++) {
            uint2 vn;
            if (j + 1 < n) vn = lin[(size_t)s_col[j + 1] * 128 + tid];
            float w = s_w[j];
            float2 g01 = __half22float2(*(const __half2*)&v.x);
            float2 g23 = __half22float2(*(const __half2*)&v.y);
            a0 = fmaf(w, g01.x, a0); a1 = fmaf(w, g01.y, a1);
            a2 = fmaf(w, g23.x, a2); a3 = fmaf(w, g23.y, a3);
            v = vn;
        }
    }
    if (OUTMODE == 2) {
        float4 b = reinterpret_cast<const float4*>(bias)[tid];
        a0 = fmaxf(a0 + b.x, 0.0f); a1 = fmaxf(a1 + b.y, 0.0f);
        a2 = fmaxf(a2 + b.z, 0.0f); a3 = fmaxf(a3 + b.w, 0.0f);
    }
    size_t o = (size_t)node * 256 + tid * 2;
    outh[o]     = __floats2half2_rn(a0, a1);
    outh[o + 1] = __floats2half2_rn(a2, a3);
}

// x [N,128] fp32 -> fp16 with aggregation; warp per node, 8 nodes/block
__global__ __launch_bounds__(256)
void k_agg128h(const float4* __restrict__ lin, __half2* __restrict__ oh) {
    int node = blockIdx.x * 8 + threadIdx.y;
    if (node >= N_NODES) return;
    int lane = threadIdx.x;
    float dii = g_dinv[node];
    float w0 = dii * dii;
    float4 a = lin[(size_t)node * 32 + lane];
    a.x *= w0; a.y *= w0; a.z *= w0; a.w *= w0;
    int beg = g_rowptr[node], end = g_rowptr[node + 1];
    if (beg < end) {
        int s = g_col[beg];
        float4 v = lin[(size_t)s * 32 + lane];
        float w = g_dinv[s] * dii;
        for (int j = beg; j < end; j++) {
            float4 vn; float wn = 0.0f;
            if (j + 1 < end) {
                int sn = g_col[j + 1];
                vn = lin[(size_t)sn * 32 + lane];
                wn = g_dinv[sn] * dii;
            }
            a.x = fmaf(w, v.x, a.x); a.y = fmaf(w, v.y, a.y);
            a.z = fmaf(w, v.z, a.z); a.w = fmaf(w, v.w, a.w);
            v = vn; w = wn;
        }
    }
    size_t o = (size_t)node * 64 + lane * 2;
    oh[o]     = __floats2half2_rn(a.x, a.y);
    oh[o + 1] = __floats2half2_rn(a.z, a.w);
}

// L4 final: aggregate (H=32, fp32 lin) + bias + log_softmax; warp per node
__global__ __launch_bounds__(256)
void k_agg_softmax32(const float* __restrict__ lin,
                     const float* __restrict__ bias,
                     float* __restrict__ out) {
    int node = blockIdx.x * 8 + threadIdx.y;
    if (node >= N_NODES) return;
    int lane = threadIdx.x;
    float dii = g_dinv[node];
    float v = lin[(size_t)node * 32 + lane] * dii * dii;
    int beg = g_rowptr[node], end = g_rowptr[node + 1];
    if (beg < end) {
        int s = g_col[beg];
        float x = lin[(size_t)s * 32 + lane];
        float w = g_dinv[s] * dii;
        for (int j = beg; j < end; j++) {
            float xn = 0.0f, wn = 0.0f;
            if (j + 1 < end) {
                int sn = g_col[j + 1];
                xn = lin[(size_t)sn * 32 + lane];
                wn = g_dinv[sn] * dii;
            }
            v = fmaf(w, x, v);
            x = xn; w = wn;
        }
    }
    v += bias[lane];
    float m = v;
#pragma unroll
    for (int o = 16; o > 0; o >>= 1)
        m = fmaxf(m, __shfl_xor_sync(0xFFFFFFFFu, m, o));
    float ex = expf(v - m);
    float s = ex;
#pragma unroll
    for (int o = 16; o > 0; o >>= 1)
        s += __shfl_xor_sync(0xFFFFFFFFu, s, o);
    out[(size_t)node * 32 + lane] = v - m - logf(s);
}

// ===========================================================================
// Launch
// ===========================================================================
static inline int cdiv(long long a, int b) { return (int)((a + b - 1) / b); }

extern "C" void kernel_launch(void* const* d_in, const int* in_sizes, int n_in,
                              void* d_out, int out_size) {
    const float* x  = (const float*)d_in[0];
    const void*  ei = d_in[1];
    const float* W1 = (const float*)d_in[2];
    const float* b1 = (const float*)d_in[3];
    const float* W2 = (const float*)d_in[4];
    const float* b2 = (const float*)d_in[5];
    const float* W3 = (const float*)d_in[6];
    const float* b3 = (const float*)d_in[7];
    const float* W4 = (const float*)d_in[8];
    const float* b4 = (const float*)d_in[9];
    float* out = (float*)d_out;

    const int E = in_sizes[1] / 2;

    float4 *buf0;
    uint4 *A, *A2, *Bh;
    cudaGetSymbolAddress((void**)&buf0, g_buf0);
    cudaGetSymbolAddress((void**)&A, g_A);
    cudaGetSymbolAddress((void**)&A2, g_A2);
    cudaGetSymbolAddress((void**)&Bh, g_Bh);

    cudaFuncSetAttribute((const void*)k_gemm_mma<1, false>,
                         cudaFuncAttributeMaxDynamicSharedMemorySize, GEMM_SMEM);
    cudaFuncSetAttribute((const void*)k_gemm_mma<2, false>,
                         cudaFuncAttributeMaxDynamicSharedMemorySize, GEMM_SMEM);
    cudaFuncSetAttribute((const void*)k_gemm_mma<3, true>,
                         cudaFuncAttributeMaxDynamicSharedMemorySize, GEMM_SMEM);

    const int MT = cdiv(N_NODES, 128);
    const __half* BW = (const __half*)Bh;

    // --- setup (zero+detect+weights) + CSR ---
    k_setup<<<1144, dim3(32, 8)>>>(ei, W1, W2, W3, W4, (__half*)Bh);
    k_count<<<cdiv(E, 256), 256>>>(ei, E);
    k_scan_dinv<<<1, 1024>>>();
    k_fill<<<cdiv(E, 256), 256>>>(ei, E);

    // --- L1: agg(x)->fp16 (A2) -> GEMM K=128 N=512 bias+relu -> fp16 h1 (A) ---
    k_agg128h<<<cdiv(N_NODES, 8), dim3(32, 8)>>>((const float4*)x, (__half2*)A2);
    k_gemm_mma<1, false><<<dim3(H1_F / 128, MT), 256, GEMM_SMEM>>>(
        A2, BW + W1T_OFF, b1, nullptr, (__half2*)A, N_NODES, IN_F, H1_F);

    // --- L2: agg(h1)->fp16 (A2) -> GEMM K=512 N=1024 bias+relu -> fp16 h2 (A) ---
    k_agg512_h<0><<<N_NODES, 128>>>((const uint2*)A, nullptr, (__half2*)A2);
    k_gemm_mma<1, false><<<dim3(H2_F / 128, MT), 256, GEMM_SMEM>>>(
        A2, BW + W2T_OFF, b2, nullptr, (__half2*)A, N_NODES, H1_F, H2_F);

    // --- L3: GEMM K=1024 N=512 raw fp16 (A2) -> agg+bias+relu -> fp16 h3 (A) ---
    k_gemm_mma<2, false><<<dim3(H3_F / 128, MT), 256, GEMM_SMEM>>>(
        A, BW + W3T_OFF, nullptr, nullptr, (__half2*)A2, N_NODES, H2_F, H3_F);
    k_agg512_h<2><<<N_NODES, 128>>>((const uint2*)A2, b3, (__half2*)A);

    // --- L4: fp16 MMA GEMM K=512 N=32 raw fp32 -> buf0 ; agg+bias+softmax ---
    k_gemm_mma<3, true><<<dim3(1, MT), 256, GEMM_SMEM>>>(
        A, BW + W4T_OFF, nullptr, (float*)buf0, nullptr, N_NODES, H3_F, OUT_F);
    k_agg_softmax32<<<cdiv(N_NODES, 8), dim3(32, 8)>>>(
        (const float*)buf0, b4, out);
}

// round 12
// speedup vs baseline: 1.0074x; 1.0074x over previous
#include <cuda_runtime.h>
#include <cuda_fp16.h>
#include <math.h>
#include <stdint.h>

#define N_NODES 10000
#define E_EDGES 160000
#define IN_F    128
#define H1_F    512
#define H2_F    1024
#define H3_F    512
#define OUT_F   32

// Weight-transpose buffer offsets (fp16 elements)
#define W1T_OFF 0
#define W2T_OFF (IN_F * H1_F)
#define W3T_OFF (W2T_OFF + H1_F * H2_F)
#define W4T_OFF (W3T_OFF + H2_F * H3_F)
#define WT_TOTAL (W4T_OFF + H3_F * OUT_F)

// ===========================================================================
// Scratch (static device globals)
// ===========================================================================
__device__ int   g_is64;
__device__ float g_dinv[N_NODES];
__device__ int   g_cnt[N_NODES];
__device__ int   g_cursor[N_NODES];
__device__ int   g_rowptr[N_NODES + 1];
__device__ int   g_col[E_EDGES];
__device__ float4 g_buf0[(size_t)N_NODES * OUT_F / 4];  // fp32 L4 lin
__device__ uint4 g_A[(size_t)N_NODES * H2_F * 2 / 16];  // fp16 activations A
__device__ uint4 g_A2[(size_t)N_NODES * H1_F * 2 / 16]; // fp16 activations B
__device__ uint4 g_Bh[(WT_TOTAL * 2 + 15) / 16];        // fp16 weights (T)

// ===========================================================================
// helpers
// ===========================================================================
__device__ __forceinline__ uint32_t smem_to_u32(const void* p) {
    uint32_t a;
    asm("{ .reg .u64 t; cvta.to.shared.u64 t, %1; cvt.u32.u64 %0, t; }"
        : "=r"(a) : "l"(p));
    return a;
}
__device__ __forceinline__ void cp_async16(uint32_t s, const void* g) {
    asm volatile("cp.async.cg.shared.global [%0], [%1], 16;"
                 :: "r"(s), "l"(__cvta_generic_to_global(g)) : "memory");
}
__device__ __forceinline__ void cp_commit() {
    asm volatile("cp.async.commit_group;" ::: "memory");
}
template <int NN>
__device__ __forceinline__ void cp_wait() {
    asm volatile("cp.async.wait_group %0;" :: "n"(NN) : "memory");
}
__device__ __forceinline__ void mma16816(float* c, const uint32_t* a,
                                         const uint32_t* b) {
    asm volatile(
        "mma.sync.aligned.m16n8k16.row.col.f32.f16.f16.f32 "
        "{%0,%1,%2,%3}, {%4,%5,%6,%7}, {%8,%9}, {%0,%1,%2,%3};"
        : "+f"(c[0]), "+f"(c[1]), "+f"(c[2]), "+f"(c[3])
        : "r"(a[0]), "r"(a[1]), "r"(a[2]), "r"(a[3]), "r"(b[0]), "r"(b[1]));
}
__device__ __forceinline__ void load_edge(const void* ei, int e, int E,
                                          int& s, int& d) {
    if (g_is64) {
        const long long* p = (const long long*)ei;
        s = (int)p[e]; d = (int)p[e + E];
    } else {
        const int* p = (const int*)ei;
        s = p[e]; d = p[e + E];
    }
}

// ===========================================================================
// Setup: zero counters + dtype detect + all-weight transpose, one kernel.
// Blocks 0..39: zero/detect.  Blocks 40..1143: W1..W4 transpose to fp16 [N,K].
// ===========================================================================
__global__ __launch_bounds__(256)
void k_setup(const void* __restrict__ ei,
             const float* __restrict__ W1, const float* __restrict__ W2,
             const float* __restrict__ W3, const float* __restrict__ W4,
             __half* __restrict__ hi) {
    const int tx = threadIdx.x, ty = threadIdx.y;   // (32, 8)
    const int tid = ty * 32 + tx;
    int b = blockIdx.x;
    if (b < 40) {
        int i = b * 256 + tid;
        if (i < N_NODES) { g_cnt[i] = 0; g_cursor[i] = 0; }
        if (b == 0) {
            if (tid == 0) g_is64 = 1;
            __syncthreads();
            if (tid < 128) {
                const long long* p = (const long long*)ei;
                long long v = p[tid];
                if (v < 0 || v >= N_NODES) atomicAnd(&g_is64, 0);
            }
        }
        return;
    }
    b -= 40;
    const float* W; int K, N; size_t off;
    if (b < 64)        { W = W1; K = IN_F; N = H1_F; off = W1T_OFF; }
    else if (b < 576)  { b -= 64;   W = W2; K = H1_F; N = H2_F; off = W2T_OFF; }
    else if (b < 1088) { b -= 576;  W = W3; K = H2_F; N = H3_F; off = W3T_OFF; }
    else               { b -= 1088; W = W4; K = H3_F; N = OUT_F; off = W4T_OFF; }
    int KT = K / 32;
    int k0 = (b % KT) * 32, n0 = (b / KT) * 32;

    __shared__ float t[32][33];
#pragma unroll
    for (int j = 0; j < 4; j++)
        t[ty + j * 8][tx] = W[(size_t)(k0 + ty + j * 8) * N + (n0 + tx)];
    __syncthreads();
#pragma unroll
    for (int j = 0; j < 4; j++) {
        float v = t[tx][ty + j * 8];
        int n = n0 + ty + j * 8;
        int k = k0 + tx;
        hi[off + (size_t)n * K + k] = __float2half_rn(v);
    }
}

// ===========================================================================
// CSR chain
// ===========================================================================
__global__ void k_count(const void* __restrict__ ei, int E) {
    int e = blockIdx.x * blockDim.x + threadIdx.x;
    if (e >= E) return;
    int s, d;
    load_edge(ei, e, E, s, d);
    atomicAdd(&g_cnt[d], 1);
}
__global__ __launch_bounds__(1024)
void k_scan_dinv() {
    __shared__ int wsum[32];
    __shared__ int s_off;
    const int tid = threadIdx.x;
    const int lane = tid & 31;
    const int wid = tid >> 5;
    if (tid == 0) s_off = 0;
    __syncthreads();
    for (int base = 0; base < N_NODES; base += 1024) {
        int i = base + tid;
        int v = (i < N_NODES) ? g_cnt[i] : 0;
        if (i < N_NODES) g_dinv[i] = rsqrtf((float)v + 1.0f);
        int x = v;
#pragma unroll
        for (int o = 1; o < 32; o <<= 1) {
            int t = __shfl_up_sync(0xFFFFFFFFu, x, o);
            if (lane >= o) x += t;
        }
        if (lane == 31) wsum[wid] = x;
        __syncthreads();
        if (wid == 0) {
            int w = wsum[lane];
#pragma unroll
            for (int o = 1; o < 32; o <<= 1) {
                int t = __shfl_up_sync(0xFFFFFFFFu, w, o);
                if (lane >= o) w += t;
            }
            wsum[lane] = w;
        }
        __syncthreads();
        int incl = x + ((wid > 0) ? wsum[wid - 1] : 0);
        int off = s_off;
        if (i < N_NODES) g_rowptr[i + 1] = off + incl;
        __syncthreads();
        if (tid == 1023) s_off = off + incl;
        __syncthreads();
    }
    if (tid == 0) g_rowptr[0] = 0;
}
__global__ void k_fill(const void* __restrict__ ei, int E) {
    int e = blockIdx.x * blockDim.x + threadIdx.x;
    if (e >= E) return;
    int s, d;
    load_edge(ei, e, E, s, d);
    int pos = g_rowptr[d] + atomicAdd(&g_cursor[d], 1);
    g_col[pos] = s;
}

// ===========================================================================
// fp16 1-pass GEMM, 3-stage cp.async pipeline. No min-blocks bound:
// accumulators must stay in registers (forcing 2 CTAs/SM spills and is a
// measured 19us regression). Occupancy 1 CTA/SM is acceptable here.
// A fp16 [M,K]; B fp16 [N,K] pre-T; fp32 acc. CTA 128x128, 8 warps 4mx2n.
// EPI: 0 bias+relu fp32 | 1 bias+relu fp16 | 2 raw fp16 | 3 raw fp32
// NG:  bounds-guard B rows / C cols against Ncols (for Ncols < 128)
// ===========================================================================
#define KC 32
#define SROW 40                      // fp16 row stride (80 B)
#define TILE_B (128 * SROW * 2)      // 10240 B
#define STAGE_B (2 * TILE_B)         // 20480 B (A, B)
#define GEMM_SMEM (3 * STAGE_B)      // 61440 B

template <int EPI, bool NG>
__global__ __launch_bounds__(256)
void k_gemm_mma(const uint4* __restrict__ A, const __half* __restrict__ B,
                const float* __restrict__ bias, float* __restrict__ C,
                __half2* __restrict__ Oh,
                int M, int K, int Ncols) {
    extern __shared__ char sm[];
    const uint32_t smb = smem_to_u32(sm);
    const int tid = threadIdx.x;
    const int lane = tid & 31;
    const int wid = tid >> 5;
    const int warp_m = wid & 3;
    const int warp_n = wid >> 2;
    const int g = lane >> 2;
    const int tig = lane & 3;
    const int mrow0 = blockIdx.y * 128;
    const int ncol0 = blockIdx.x * 128;
    const int KU = K >> 3;
    const int nChunks = K / KC;

    float acc[2][8][4];
#pragma unroll
    for (int i = 0; i < 2; i++)
#pragma unroll
        for (int j = 0; j < 8; j++)
#pragma unroll
            for (int q = 0; q < 4; q++) acc[i][j][q] = 0.0f;

    auto load_chunk = [&](int it, int st) {
        const int ku0 = it * (KC / 8);
        const uint32_t sb = smb + st * STAGE_B;
#pragma unroll
        for (int q = tid; q < 512; q += 256) {
            int row = q >> 2;
            int cb = q & 3;
            uint32_t so = (uint32_t)(row * 80 + cb * 16);
            int gm = mrow0 + row;
            if (gm < M) {
                cp_async16(sb + so, A + (size_t)gm * KU + ku0 + cb);
            } else {
                *(uint4*)(sm + st * STAGE_B + so) = make_uint4(0, 0, 0, 0);
            }
            int brow = ncol0 + row;
            if (!NG || brow < Ncols) {
                size_t bb = (size_t)brow * K + it * KC + cb * 8;
                cp_async16(sb + TILE_B + so, B + bb);
            } else {
                *(uint4*)(sm + st * STAGE_B + TILE_B + so) = make_uint4(0, 0, 0, 0);
            }
        }
        cp_commit();
    };

    load_chunk(0, 0);
    load_chunk(1, 1);
    for (int it = 0; it < nChunks; it++) {
        const int cur = it % 3;
        if (it + 2 < nChunks) {
            load_chunk(it + 2, (it + 2) % 3);
            cp_wait<2>();
        } else if (it + 1 < nChunks) {
            cp_wait<1>();
        } else {
            cp_wait<0>();
        }
        __syncthreads();

        const __half* sA = (const __half*)(sm + cur * STAGE_B);
        const __half* sB = (const __half*)(sm + cur * STAGE_B + TILE_B);

#pragma unroll
        for (int ks = 0; ks < KC / 16; ks++) {
            const int k0 = ks * 16;
            uint32_t ah[2][4];
#pragma unroll
            for (int mt = 0; mt < 2; mt++) {
                int r0 = warp_m * 32 + mt * 16 + g;
                int c0 = k0 + tig * 2;
                ah[mt][0] = *(const uint32_t*)(sA + r0 * SROW + c0);
                ah[mt][1] = *(const uint32_t*)(sA + (r0 + 8) * SROW + c0);
                ah[mt][2] = *(const uint32_t*)(sA + r0 * SROW + c0 + 8);
                ah[mt][3] = *(const uint32_t*)(sA + (r0 + 8) * SROW + c0 + 8);
            }
            uint32_t bh[8][2];
#pragma unroll
            for (int nt = 0; nt < 8; nt++) {
                int r0 = warp_n * 64 + nt * 8 + g;
                int c0 = k0 + tig * 2;
                bh[nt][0] = *(const uint32_t*)(sB + r0 * SROW + c0);
                bh[nt][1] = *(const uint32_t*)(sB + r0 * SROW + c0 + 8);
            }
#pragma unroll
            for (int mt = 0; mt < 2; mt++)
#pragma unroll
                for (int nt = 0; nt < 8; nt++) mma16816(acc[mt][nt], ah[mt], bh[nt]);
        }
        __syncthreads();
    }

    // Epilogue
#pragma unroll
    for (int mt = 0; mt < 2; mt++) {
        int rbase = mrow0 + warp_m * 32 + mt * 16;
#pragma unroll
        for (int nt = 0; nt < 8; nt++) {
            int col = ncol0 + warp_n * 64 + nt * 8 + tig * 2;
            if (NG && col >= Ncols) continue;
            float b0 = 0.0f, b1 = 0.0f;
            if (EPI == 0 || EPI == 1) { b0 = bias[col]; b1 = bias[col + 1]; }
#pragma unroll
            for (int half = 0; half < 2; half++) {
                int r = rbase + g + half * 8;
                if (r >= M) continue;
                float v0 = acc[mt][nt][half * 2 + 0] + b0;
                float v1 = acc[mt][nt][half * 2 + 1] + b1;
                if (EPI == 0 || EPI == 1) { v0 = fmaxf(v0, 0.0f); v1 = fmaxf(v1, 0.0f); }
                if (EPI == 0 || EPI == 3) {
                    *(float2*)(C + (size_t)r * Ncols + col) = make_float2(v0, v1);
                } else {
                    Oh[((size_t)r * Ncols + col) >> 1] = __floats2half2_rn(v0, v1);
                }
            }
        }
    }
}

// ===========================================================================
// Aggregations (weights rebuilt from g_dinv)
// ===========================================================================
// fp16 in, H=512, block(128) per node.
// OUTMODE 0: fp16 out (no bias) | OUTMODE 2: bias+relu -> fp16 out
template <int OUTMODE>
__global__ __launch_bounds__(128)
void k_agg512_h(const uint2* __restrict__ lin,       // fp16 [N,512] as uint2
                const float* __restrict__ bias,
                __half2* __restrict__ outh) {
    const int node = blockIdx.x;
    const int tid = threadIdx.x;
    float dii = g_dinv[node];
    float w0 = dii * dii;

    uint2 sv = lin[(size_t)node * 128 + tid];
    float2 f01 = __half22float2(*(const __half2*)&sv.x);
    float2 f23 = __half22float2(*(const __half2*)&sv.y);
    float a0 = f01.x * w0, a1 = f01.y * w0, a2 = f23.x * w0, a3 = f23.y * w0;

    __shared__ int   s_col[128];
    __shared__ float s_w[128];
    const int beg = g_rowptr[node];
    const int end = g_rowptr[node + 1];
    for (int j0 = beg; j0 < end; j0 += 128) {
        int n = min(128, end - j0);
        __syncthreads();
        if (tid < n) {
            int c = g_col[j0 + tid];
            s_col[tid] = c;
            s_w[tid] = g_dinv[c] * dii;
        }
        __syncthreads();
        // 1-deep row prefetch
        uint2 v = lin[(size_t)s_col[0] * 128 + tid];
        for (int j = 0; j < n; j++) {
            uint2 vn;
            if (j + 1 < n) vn = lin[(size_t)s_col[j + 1] * 128 + tid];
            float w = s_w[j];
            float2 g01 = __half22float2(*(const __half2*)&v.x);
            float2 g23 = __half22float2(*(const __half2*)&v.y);
            a0 = fmaf(w, g01.x, a0); a1 = fmaf(w, g01.y, a1);
            a2 = fmaf(w, g23.x, a2); a3 = fmaf(w, g23.y, a3);
            v = vn;
        }
    }
    if (OUTMODE == 2) {
        float4 b = reinterpret_cast<const float4*>(bias)[tid];
        a0 = fmaxf(a0 + b.x, 0.0f); a1 = fmaxf(a1 + b.y, 0.0f);
        a2 = fmaxf(a2 + b.z, 0.0f); a3 = fmaxf(a3 + b.w, 0.0f);
    }
    size_t o = (size_t)node * 256 + tid * 2;
    outh[o]     = __floats2half2_rn(a0, a1);
    outh[o + 1] = __floats2half2_rn(a2, a3);
}

// x [N,128] fp32 -> fp16 with aggregation; warp per node, 8 nodes/block
__global__ __launch_bounds__(256)
void k_agg128h(const float4* __restrict__ lin, __half2* __restrict__ oh) {
    int node = blockIdx.x * 8 + threadIdx.y;
    if (node >= N_NODES) return;
    int lane = threadIdx.x;
    float dii = g_dinv[node];
    float w0 = dii * dii;
    float4 a = lin[(size_t)node * 32 + lane];
    a.x *= w0; a.y *= w0; a.z *= w0; a.w *= w0;
    int beg = g_rowptr[node], end = g_rowptr[node + 1];
    if (beg < end) {
        int s = g_col[beg];
        float4 v = lin[(size_t)s * 32 + lane];
        float w = g_dinv[s] * dii;
        for (int j = beg; j < end; j++) {
            float4 vn; float wn = 0.0f;
            if (j + 1 < end) {
                int sn = g_col[j + 1];
                vn = lin[(size_t)sn * 32 + lane];
                wn = g_dinv[sn] * dii;
            }
            a.x = fmaf(w, v.x, a.x); a.y = fmaf(w, v.y, a.y);
            a.z = fmaf(w, v.z, a.z); a.w = fmaf(w, v.w, a.w);
            v = vn; w = wn;
        }
    }
    size_t o = (size_t)node * 64 + lane * 2;
    oh[o]     = __floats2half2_rn(a.x, a.y);
    oh[o + 1] = __floats2half2_rn(a.z, a.w);
}

// L4 final: aggregate (H=32, fp32 lin) + bias + log_softmax; warp per node
__global__ __launch_bounds__(256)
void k_agg_softmax32(const float* __restrict__ lin,
                     const float* __restrict__ bias,
                     float* __restrict__ out) {
    int node = blockIdx.x * 8 + threadIdx.y;
    if (node >= N_NODES) return;
    int lane = threadIdx.x;
    float dii = g_dinv[node];
    float v = lin[(size_t)node * 32 + lane] * dii * dii;
    int beg = g_rowptr[node], end = g_rowptr[node + 1];
    if (beg < end) {
        int s = g_col[beg];
        float x = lin[(size_t)s * 32 + lane];
        float w = g_dinv[s] * dii;
        for (int j = beg; j < end; j++) {
            float xn = 0.0f, wn = 0.0f;
            if (j + 1 < end) {
                int sn = g_col[j + 1];
                xn = lin[(size_t)sn * 32 + lane];
                wn = g_dinv[sn] * dii;
            }
            v = fmaf(w, x, v);
            x = xn; w = wn;
        }
    }
    v += bias[lane];
    float m = v;
#pragma unroll
    for (int o = 16; o > 0; o >>= 1)
        m = fmaxf(m, __shfl_xor_sync(0xFFFFFFFFu, m, o));
    float ex = expf(v - m);
    float s = ex;
#pragma unroll
    for (int o = 16; o > 0; o >>= 1)
        s += __shfl_xor_sync(0xFFFFFFFFu, s, o);
    out[(size_t)node * 32 + lane] = v - m - logf(s);
}

// ===========================================================================
// Launch
// ===========================================================================
static inline int cdiv(long long a, int b) { return (int)((a + b - 1) / b); }

extern "C" void kernel_launch(void* const* d_in, const int* in_sizes, int n_in,
                              void* d_out, int out_size) {
    const float* x  = (const float*)d_in[0];
    const void*  ei = d_in[1];
    const float* W1 = (const float*)d_in[2];
    const float* b1 = (const float*)d_in[3];
    const float* W2 = (const float*)d_in[4];
    const float* b2 = (const float*)d_in[5];
    const float* W3 = (const float*)d_in[6];
    const float* b3 = (const float*)d_in[7];
    const float* W4 = (const float*)d_in[8];
    const float* b4 = (const float*)d_in[9];
    float* out = (float*)d_out;

    const int E = in_sizes[1] / 2;

    float4 *buf0;
    uint4 *A, *A2, *Bh;
    cudaGetSymbolAddress((void**)&buf0, g_buf0);
    cudaGetSymbolAddress((void**)&A, g_A);
    cudaGetSymbolAddress((void**)&A2, g_A2);
    cudaGetSymbolAddress((void**)&Bh, g_Bh);

    cudaFuncSetAttribute((const void*)k_gemm_mma<1, false>,
                         cudaFuncAttributeMaxDynamicSharedMemorySize, GEMM_SMEM);
    cudaFuncSetAttribute((const void*)k_gemm_mma<2, false>,
                         cudaFuncAttributeMaxDynamicSharedMemorySize, GEMM_SMEM);
    cudaFuncSetAttribute((const void*)k_gemm_mma<3, true>,
                         cudaFuncAttributeMaxDynamicSharedMemorySize, GEMM_SMEM);

    const int MT = cdiv(N_NODES, 128);
    const __half* BW = (const __half*)Bh;

    // --- setup (zero+detect+weights) + CSR ---
    k_setup<<<1144, dim3(32, 8)>>>(ei, W1, W2, W3, W4, (__half*)Bh);
    k_count<<<cdiv(E, 256), 256>>>(ei, E);
    k_scan_dinv<<<1, 1024>>>();
    k_fill<<<cdiv(E, 256), 256>>>(ei, E);

    // --- L1: agg(x)->fp16 (A2) -> GEMM K=128 N=512 bias+relu -> fp16 h1 (A) ---
    k_agg128h<<<cdiv(N_NODES, 8), dim3(32, 8)>>>((const float4*)x, (__half2*)A2);
    k_gemm_mma<1, false><<<dim3(H1_F / 128, MT), 256, GEMM_SMEM>>>(
        A2, BW + W1T_OFF, b1, nullptr, (__half2*)A, N_NODES, IN_F, H1_F);

    // --- L2: agg(h1)->fp16 (A2) -> GEMM K=512 N=1024 bias+relu -> fp16 h2 (A) ---
    k_agg512_h<0><<<N_NODES, 128>>>((const uint2*)A, nullptr, (__half2*)A2);
    k_gemm_mma<1, false><<<dim3(H2_F / 128, MT), 256, GEMM_SMEM>>>(
        A2, BW + W2T_OFF, b2, nullptr, (__half2*)A, N_NODES, H1_F, H2_F);

    // --- L3: GEMM K=1024 N=512 raw fp16 (A2) -> agg+bias+relu -> fp16 h3 (A) ---
    k_gemm_mma<2, false><<<dim3(H3_F / 128, MT), 256, GEMM_SMEM>>>(
        A, BW + W3T_OFF, nullptr, nullptr, (__half2*)A2, N_NODES, H2_F, H3_F);
    k_agg512_h<2><<<N_NODES, 128>>>((const uint2*)A2, b3, (__half2*)A);

    // --- L4: fp16 MMA GEMM K=512 N=32 raw fp32 -> buf0 ; agg+bias+softmax ---
    k_gemm_mma<3, true><<<dim3(1, MT), 256, GEMM_SMEM>>>(
        A, BW + W4T_OFF, nullptr, (float*)buf0, nullptr, N_NODES, H3_F, OUT_F);
    k_agg_softmax32<<<cdiv(N_NODES, 8), dim3(32, 8)>>>(
        (const float*)buf0, b4, out);
}

// round 13
// speedup vs baseline: 1.1036x; 1.0955x over previous
#include <cuda_runtime.h>
#include <cuda_fp16.h>
#include <math.h>
#include <stdint.h>

#define N_NODES 10000
#define E_EDGES 160000
#define IN_F    128
#define H1_F    512
#define H2_F    1024
#define H3_F    512
#define OUT_F   32

// Weight-transpose buffer offsets (fp16 elements)
#define W1T_OFF 0
#define W2T_OFF (IN_F * H1_F)
#define W3T_OFF (W2T_OFF + H1_F * H2_F)
#define W4T_OFF (W3T_OFF + H2_F * H3_F)
#define WT_TOTAL (W4T_OFF + H3_F * OUT_F)

// ===========================================================================
// Scratch (static device globals)
// ===========================================================================
__device__ int   g_is64;
__device__ float g_dinv[N_NODES];
__device__ int   g_cnt[N_NODES];
__device__ int   g_cursor[N_NODES];
__device__ int   g_rowptr[N_NODES + 1];
__device__ int   g_col[E_EDGES];
__device__ float g_wt[E_EDGES];                         // independent weight stream
__device__ float4 g_buf0[(size_t)N_NODES * OUT_F / 4];  // fp32 L4 lin
__device__ uint4 g_A[(size_t)N_NODES * H2_F * 2 / 16];  // fp16 activations A
__device__ uint4 g_A2[(size_t)N_NODES * H1_F * 2 / 16]; // fp16 activations B
__device__ uint4 g_Bh[(WT_TOTAL * 2 + 15) / 16];        // fp16 weights (T)

// ===========================================================================
// helpers
// ===========================================================================
__device__ __forceinline__ uint32_t smem_to_u32(const void* p) {
    uint32_t a;
    asm("{ .reg .u64 t; cvta.to.shared.u64 t, %1; cvt.u32.u64 %0, t; }"
        : "=r"(a) : "l"(p));
    return a;
}
__device__ __forceinline__ void cp_async16(uint32_t s, const void* g) {
    asm volatile("cp.async.cg.shared.global [%0], [%1], 16;"
                 :: "r"(s), "l"(__cvta_generic_to_global(g)) : "memory");
}
__device__ __forceinline__ void cp_commit() {
    asm volatile("cp.async.commit_group;" ::: "memory");
}
template <int NN>
__device__ __forceinline__ void cp_wait() {
    asm volatile("cp.async.wait_group %0;" :: "n"(NN) : "memory");
}
__device__ __forceinline__ void mma16816(float* c, const uint32_t* a,
                                         const uint32_t* b) {
    asm volatile(
        "mma.sync.aligned.m16n8k16.row.col.f32.f16.f16.f32 "
        "{%0,%1,%2,%3}, {%4,%5,%6,%7}, {%8,%9}, {%0,%1,%2,%3};"
        : "+f"(c[0]), "+f"(c[1]), "+f"(c[2]), "+f"(c[3])
        : "r"(a[0]), "r"(a[1]), "r"(a[2]), "r"(a[3]), "r"(b[0]), "r"(b[1]));
}
__device__ __forceinline__ void load_edge(const void* ei, int e, int E,
                                          int& s, int& d) {
    if (g_is64) {
        const long long* p = (const long long*)ei;
        s = (int)p[e]; d = (int)p[e + E];
    } else {
        const int* p = (const int*)ei;
        s = p[e]; d = p[e + E];
    }
}

// ===========================================================================
// Setup: zero counters + dtype detect + all-weight transpose, one kernel.
// Blocks 0..39: zero/detect.  Blocks 40..1143: W1..W4 transpose to fp16 [N,K].
// ===========================================================================
__global__ __launch_bounds__(256)
void k_setup(const void* __restrict__ ei,
             const float* __restrict__ W1, const float* __restrict__ W2,
             const float* __restrict__ W3, const float* __restrict__ W4,
             __half* __restrict__ hi) {
    const int tx = threadIdx.x, ty = threadIdx.y;   // (32, 8)
    const int tid = ty * 32 + tx;
    int b = blockIdx.x;
    if (b < 40) {
        int i = b * 256 + tid;
        if (i < N_NODES) { g_cnt[i] = 0; g_cursor[i] = 0; }
        if (b == 0) {
            if (tid == 0) g_is64 = 1;
            __syncthreads();
            if (tid < 128) {
                const long long* p = (const long long*)ei;
                long long v = p[tid];
                if (v < 0 || v >= N_NODES) atomicAnd(&g_is64, 0);
            }
        }
        return;
    }
    b -= 40;
    const float* W; int K, N; size_t off;
    if (b < 64)        { W = W1; K = IN_F; N = H1_F; off = W1T_OFF; }
    else if (b < 576)  { b -= 64;   W = W2; K = H1_F; N = H2_F; off = W2T_OFF; }
    else if (b < 1088) { b -= 576;  W = W3; K = H2_F; N = H3_F; off = W3T_OFF; }
    else               { b -= 1088; W = W4; K = H3_F; N = OUT_F; off = W4T_OFF; }
    int KT = K / 32;
    int k0 = (b % KT) * 32, n0 = (b / KT) * 32;

    __shared__ float t[32][33];
#pragma unroll
    for (int j = 0; j < 4; j++)
        t[ty + j * 8][tx] = W[(size_t)(k0 + ty + j * 8) * N + (n0 + tx)];
    __syncthreads();
#pragma unroll
    for (int j = 0; j < 4; j++) {
        float v = t[tx][ty + j * 8];
        int n = n0 + ty + j * 8;
        int k = k0 + tx;
        hi[off + (size_t)n * K + k] = __float2half_rn(v);
    }
}

// ===========================================================================
// CSR chain (direct edge reads; col + wt streams as in round 10)
// ===========================================================================
__global__ void k_count(const void* __restrict__ ei, int E) {
    int e = blockIdx.x * blockDim.x + threadIdx.x;
    if (e >= E) return;
    int s, d;
    load_edge(ei, e, E, s, d);
    atomicAdd(&g_cnt[d], 1);
}
__global__ __launch_bounds__(1024)
void k_scan_dinv() {
    __shared__ int wsum[32];
    __shared__ int s_off;
    const int tid = threadIdx.x;
    const int lane = tid & 31;
    const int wid = tid >> 5;
    if (tid == 0) s_off = 0;
    __syncthreads();
    for (int base = 0; base < N_NODES; base += 1024) {
        int i = base + tid;
        int v = (i < N_NODES) ? g_cnt[i] : 0;
        if (i < N_NODES) g_dinv[i] = rsqrtf((float)v + 1.0f);
        int x = v;
#pragma unroll
        for (int o = 1; o < 32; o <<= 1) {
            int t = __shfl_up_sync(0xFFFFFFFFu, x, o);
            if (lane >= o) x += t;
        }
        if (lane == 31) wsum[wid] = x;
        __syncthreads();
        if (wid == 0) {
            int w = wsum[lane];
#pragma unroll
            for (int o = 1; o < 32; o <<= 1) {
                int t = __shfl_up_sync(0xFFFFFFFFu, w, o);
                if (lane >= o) w += t;
            }
            wsum[lane] = w;
        }
        __syncthreads();
        int incl = x + ((wid > 0) ? wsum[wid - 1] : 0);
        int off = s_off;
        if (i < N_NODES) g_rowptr[i + 1] = off + incl;
        __syncthreads();
        if (tid == 1023) s_off = off + incl;
        __syncthreads();
    }
    if (tid == 0) g_rowptr[0] = 0;
}
__global__ void k_fill(const void* __restrict__ ei, int E) {
    int e = blockIdx.x * blockDim.x + threadIdx.x;
    if (e >= E) return;
    int s, d;
    load_edge(ei, e, E, s, d);
    float w = g_dinv[s] * g_dinv[d];
    int pos = g_rowptr[d] + atomicAdd(&g_cursor[d], 1);
    g_col[pos] = s;
    g_wt[pos]  = w;
}

// ===========================================================================
// fp16 1-pass GEMM, 3-stage cp.async pipeline. No min-blocks bound
// (forcing 2 CTAs/SM spills accumulators: measured regression).
// A fp16 [M,K]; B fp16 [N,K] pre-T; fp32 acc. CTA 128x128, 8 warps 4mx2n.
// EPI: 0 bias+relu fp32 | 1 bias+relu fp16 | 2 raw fp16 | 3 raw fp32
// NG:  bounds-guard B rows / C cols against Ncols (for Ncols < 128)
// ===========================================================================
#define KC 32
#define SROW 40                      // fp16 row stride (80 B)
#define TILE_B (128 * SROW * 2)      // 10240 B
#define STAGE_B (2 * TILE_B)         // 20480 B (A, B)
#define GEMM_SMEM (3 * STAGE_B)      // 61440 B

template <int EPI, bool NG>
__global__ __launch_bounds__(256)
void k_gemm_mma(const uint4* __restrict__ A, const __half* __restrict__ B,
                const float* __restrict__ bias, float* __restrict__ C,
                __half2* __restrict__ Oh,
                int M, int K, int Ncols) {
    extern __shared__ char sm[];
    const uint32_t smb = smem_to_u32(sm);
    const int tid = threadIdx.x;
    const int lane = tid & 31;
    const int wid = tid >> 5;
    const int warp_m = wid & 3;
    const int warp_n = wid >> 2;
    const int g = lane >> 2;
    const int tig = lane & 3;
    const int mrow0 = blockIdx.y * 128;
    const int ncol0 = blockIdx.x * 128;
    const int KU = K >> 3;
    const int nChunks = K / KC;

    float acc[2][8][4];
#pragma unroll
    for (int i = 0; i < 2; i++)
#pragma unroll
        for (int j = 0; j < 8; j++)
#pragma unroll
            for (int q = 0; q < 4; q++) acc[i][j][q] = 0.0f;

    auto load_chunk = [&](int it, int st) {
        const int ku0 = it * (KC / 8);
        const uint32_t sb = smb + st * STAGE_B;
#pragma unroll
        for (int q = tid; q < 512; q += 256) {
            int row = q >> 2;
            int cb = q & 3;
            uint32_t so = (uint32_t)(row * 80 + cb * 16);
            int gm = mrow0 + row;
            if (gm < M) {
                cp_async16(sb + so, A + (size_t)gm * KU + ku0 + cb);
            } else {
                *(uint4*)(sm + st * STAGE_B + so) = make_uint4(0, 0, 0, 0);
            }
            int brow = ncol0 + row;
            if (!NG || brow < Ncols) {
                size_t bb = (size_t)brow * K + it * KC + cb * 8;
                cp_async16(sb + TILE_B + so, B + bb);
            } else {
                *(uint4*)(sm + st * STAGE_B + TILE_B + so) = make_uint4(0, 0, 0, 0);
            }
        }
        cp_commit();
    };

    load_chunk(0, 0);
    load_chunk(1, 1);
    for (int it = 0; it < nChunks; it++) {
        const int cur = it % 3;
        if (it + 2 < nChunks) {
            load_chunk(it + 2, (it + 2) % 3);
            cp_wait<2>();
        } else if (it + 1 < nChunks) {
            cp_wait<1>();
        } else {
            cp_wait<0>();
        }
        __syncthreads();

        const __half* sA = (const __half*)(sm + cur * STAGE_B);
        const __half* sB = (const __half*)(sm + cur * STAGE_B + TILE_B);

#pragma unroll
        for (int ks = 0; ks < KC / 16; ks++) {
            const int k0 = ks * 16;
            uint32_t ah[2][4];
#pragma unroll
            for (int mt = 0; mt < 2; mt++) {
                int r0 = warp_m * 32 + mt * 16 + g;
                int c0 = k0 + tig * 2;
                ah[mt][0] = *(const uint32_t*)(sA + r0 * SROW + c0);
                ah[mt][1] = *(const uint32_t*)(sA + (r0 + 8) * SROW + c0);
                ah[mt][2] = *(const uint32_t*)(sA + r0 * SROW + c0 + 8);
                ah[mt][3] = *(const uint32_t*)(sA + (r0 + 8) * SROW + c0 + 8);
            }
            uint32_t bh[8][2];
#pragma unroll
            for (int nt = 0; nt < 8; nt++) {
                int r0 = warp_n * 64 + nt * 8 + g;
                int c0 = k0 + tig * 2;
                bh[nt][0] = *(const uint32_t*)(sB + r0 * SROW + c0);
                bh[nt][1] = *(const uint32_t*)(sB + r0 * SROW + c0 + 8);
            }
#pragma unroll
            for (int mt = 0; mt < 2; mt++)
#pragma unroll
                for (int nt = 0; nt < 8; nt++) mma16816(acc[mt][nt], ah[mt], bh[nt]);
        }
        __syncthreads();
    }

    // Epilogue
#pragma unroll
    for (int mt = 0; mt < 2; mt++) {
        int rbase = mrow0 + warp_m * 32 + mt * 16;
#pragma unroll
        for (int nt = 0; nt < 8; nt++) {
            int col = ncol0 + warp_n * 64 + nt * 8 + tig * 2;
            if (NG && col >= Ncols) continue;
            float b0 = 0.0f, b1 = 0.0f;
            if (EPI == 0 || EPI == 1) { b0 = bias[col]; b1 = bias[col + 1]; }
#pragma unroll
            for (int half = 0; half < 2; half++) {
                int r = rbase + g + half * 8;
                if (r >= M) continue;
                float v0 = acc[mt][nt][half * 2 + 0] + b0;
                float v1 = acc[mt][nt][half * 2 + 1] + b1;
                if (EPI == 0 || EPI == 1) { v0 = fmaxf(v0, 0.0f); v1 = fmaxf(v1, 0.0f); }
                if (EPI == 0 || EPI == 3) {
                    *(float2*)(C + (size_t)r * Ncols + col) = make_float2(v0, v1);
                } else {
                    Oh[((size_t)r * Ncols + col) >> 1] = __floats2half2_rn(v0, v1);
                }
            }
        }
    }
}

// ===========================================================================
// Aggregations — round-10 structure: independent g_col/g_wt streams,
// compiler-scheduled inner loops (no manual prefetch).
// ===========================================================================
// fp16 in, H=512, block(128) per node.
// OUTMODE 0: fp16 out (no bias) | OUTMODE 2: bias+relu -> fp16 out
template <int OUTMODE>
__global__ __launch_bounds__(128)
void k_agg512_h(const uint2* __restrict__ lin,       // fp16 [N,512] as uint2
                const float* __restrict__ bias,
                __half2* __restrict__ outh) {
    const int node = blockIdx.x;
    const int tid = threadIdx.x;
    float dii = g_dinv[node];
    float w0 = dii * dii;

    uint2 sv = lin[(size_t)node * 128 + tid];
    float2 f01 = __half22float2(*(const __half2*)&sv.x);
    float2 f23 = __half22float2(*(const __half2*)&sv.y);
    float a0 = f01.x * w0, a1 = f01.y * w0, a2 = f23.x * w0, a3 = f23.y * w0;

    __shared__ int   s_col[128];
    __shared__ float s_w[128];
    const int beg = g_rowptr[node];
    const int end = g_rowptr[node + 1];
    for (int j0 = beg; j0 < end; j0 += 128) {
        int n = min(128, end - j0);
        __syncthreads();
        if (tid < n) { s_col[tid] = g_col[j0 + tid]; s_w[tid] = g_wt[j0 + tid]; }
        __syncthreads();
        for (int j = 0; j < n; j++) {
            int s = s_col[j];
            float w = s_w[j];
            uint2 v = lin[(size_t)s * 128 + tid];
            float2 g01 = __half22float2(*(const __half2*)&v.x);
            float2 g23 = __half22float2(*(const __half2*)&v.y);
            a0 = fmaf(w, g01.x, a0); a1 = fmaf(w, g01.y, a1);
            a2 = fmaf(w, g23.x, a2); a3 = fmaf(w, g23.y, a3);
        }
    }
    if (OUTMODE == 2) {
        float4 b = reinterpret_cast<const float4*>(bias)[tid];
        a0 = fmaxf(a0 + b.x, 0.0f); a1 = fmaxf(a1 + b.y, 0.0f);
        a2 = fmaxf(a2 + b.z, 0.0f); a3 = fmaxf(a3 + b.w, 0.0f);
    }
    size_t o = (size_t)node * 256 + tid * 2;
    outh[o]     = __floats2half2_rn(a0, a1);
    outh[o + 1] = __floats2half2_rn(a2, a3);
}

// x [N,128] fp32 -> fp16 with aggregation; warp per node, 8 nodes/block
__global__ __launch_bounds__(256)
void k_agg128h(const float4* __restrict__ lin, __half2* __restrict__ oh) {
    int node = blockIdx.x * 8 + threadIdx.y;
    if (node >= N_NODES) return;
    int lane = threadIdx.x;
    float dii = g_dinv[node];
    float w0 = dii * dii;
    float4 a = lin[(size_t)node * 32 + lane];
    a.x *= w0; a.y *= w0; a.z *= w0; a.w *= w0;
    int beg = g_rowptr[node], end = g_rowptr[node + 1];
    for (int j = beg; j < end; j++) {
        int s = g_col[j];
        float w = g_wt[j];
        float4 v = lin[(size_t)s * 32 + lane];
        a.x = fmaf(w, v.x, a.x); a.y = fmaf(w, v.y, a.y);
        a.z = fmaf(w, v.z, a.z); a.w = fmaf(w, v.w, a.w);
    }
    size_t o = (size_t)node * 64 + lane * 2;
    oh[o]     = __floats2half2_rn(a.x, a.y);
    oh[o + 1] = __floats2half2_rn(a.z, a.w);
}

// L4 final: aggregate (H=32, fp32 lin) + bias + log_softmax; warp per node
__global__ __launch_bounds__(256)
void k_agg_softmax32(const float* __restrict__ lin,
                     const float* __restrict__ bias,
                     float* __restrict__ out) {
    int node = blockIdx.x * 8 + threadIdx.y;
    if (node >= N_NODES) return;
    int lane = threadIdx.x;
    float dii = g_dinv[node];
    float v = lin[(size_t)node * 32 + lane] * dii * dii;
    int beg = g_rowptr[node], end = g_rowptr[node + 1];
    for (int j = beg; j < end; j++) {
        int s = g_col[j];
        float w = g_wt[j];
        v = fmaf(w, lin[(size_t)s * 32 + lane], v);
    }
    v += bias[lane];
    float m = v;
#pragma unroll
    for (int o = 16; o > 0; o >>= 1)
        m = fmaxf(m, __shfl_xor_sync(0xFFFFFFFFu, m, o));
    float ex = expf(v - m);
    float s = ex;
#pragma unroll
    for (int o = 16; o > 0; o >>= 1)
        s += __shfl_xor_sync(0xFFFFFFFFu, s, o);
    out[(size_t)node * 32 + lane] = v - m - logf(s);
}

// ===========================================================================
// Launch
// ===========================================================================
static inline int cdiv(long long a, int b) { return (int)((a + b - 1) / b); }

extern "C" void kernel_launch(void* const* d_in, const int* in_sizes, int n_in,
                              void* d_out, int out_size) {
    const float* x  = (const float*)d_in[0];
    const void*  ei = d_in[1];
    const float* W1 = (const float*)d_in[2];
    const float* b1 = (const float*)d_in[3];
    const float* W2 = (const float*)d_in[4];
    const float* b2 = (const float*)d_in[5];
    const float* W3 = (const float*)d_in[6];
    const float* b3 = (const float*)d_in[7];
    const float* W4 = (const float*)d_in[8];
    const float* b4 = (const float*)d_in[9];
    float* out = (float*)d_out;

    const int E = in_sizes[1] / 2;

    float4 *buf0;
    uint4 *A, *A2, *Bh;
    cudaGetSymbolAddress((void**)&buf0, g_buf0);
    cudaGetSymbolAddress((void**)&A, g_A);
    cudaGetSymbolAddress((void**)&A2, g_A2);
    cudaGetSymbolAddress((void**)&Bh, g_Bh);

    cudaFuncSetAttribute((const void*)k_gemm_mma<1, false>,
                         cudaFuncAttributeMaxDynamicSharedMemorySize, GEMM_SMEM);
    cudaFuncSetAttribute((const void*)k_gemm_mma<2, false>,
                         cudaFuncAttributeMaxDynamicSharedMemorySize, GEMM_SMEM);
    cudaFuncSetAttribute((const void*)k_gemm_mma<3, true>,
                         cudaFuncAttributeMaxDynamicSharedMemorySize, GEMM_SMEM);

    const int MT = cdiv(N_NODES, 128);
    const __half* BW = (const __half*)Bh;

    // --- setup (zero+detect+weights) + CSR ---
    k_setup<<<1144, dim3(32, 8)>>>(ei, W1, W2, W3, W4, (__half*)Bh);
    k_count<<<cdiv(E, 256), 256>>>(ei, E);
    k_scan_dinv<<<1, 1024>>>();
    k_fill<<<cdiv(E, 256), 256>>>(ei, E);

    // --- L1: agg(x)->fp16 (A2) -> GEMM K=128 N=512 bias+relu -> fp16 h1 (A) ---
    k_agg128h<<<cdiv(N_NODES, 8), dim3(32, 8)>>>((const float4*)x, (__half2*)A2);
    k_gemm_mma<1, false><<<dim3(H1_F / 128, MT), 256, GEMM_SMEM>>>(
        A2, BW + W1T_OFF, b1, nullptr, (__half2*)A, N_NODES, IN_F, H1_F);

    // --- L2: agg(h1)->fp16 (A2) -> GEMM K=512 N=1024 bias+relu -> fp16 h2 (A) ---
    k_agg512_h<0><<<N_NODES, 128>>>((const uint2*)A, nullptr, (__half2*)A2);
    k_gemm_mma<1, false><<<dim3(H2_F / 128, MT), 256, GEMM_SMEM>>>(
        A2, BW + W2T_OFF, b2, nullptr, (__half2*)A, N_NODES, H1_F, H2_F);

    // --- L3: GEMM K=1024 N=512 raw fp16 (A2) -> agg+bias+relu -> fp16 h3 (A) ---
    k_gemm_mma<2, false><<<dim3(H3_F / 128, MT), 256, GEMM_SMEM>>>(
        A, BW + W3T_OFF, nullptr, nullptr, (__half2*)A2, N_NODES, H2_F, H3_F);
    k_agg512_h<2><<<N_NODES, 128>>>((const uint2*)A2, b3, (__half2*)A);

    // --- L4: fp16 MMA GEMM K=512 N=32 raw fp32 -> buf0 ; agg+bias+softmax ---
    k_gemm_mma<3, true><<<dim3(1, MT), 256, GEMM_SMEM>>>(
        A, BW + W4T_OFF, nullptr, (float*)buf0, nullptr, N_NODES, H3_F, OUT_F);
    k_agg_softmax32<<<cdiv(N_NODES, 8), dim3(32, 8)>>>(
        (const float*)buf0, b4, out);
}

// round 14
// speedup vs baseline: 1.1128x; 1.0084x over previous
#include <cuda_runtime.h>
#include <cuda_fp16.h>
#include <math.h>
#include <stdint.h>

#define N_NODES 10000
#define E_EDGES 160000
#define IN_F    128
#define H1_F    512
#define H2_F    1024
#define H3_F    512
#define OUT_F   32

// Weight-transpose buffer offsets (fp16 elements)
#define W1T_OFF 0
#define W2T_OFF (IN_F * H1_F)
#define W3T_OFF (W2T_OFF + H1_F * H2_F)
#define W4T_OFF (W3T_OFF + H2_F * H3_F)
#define WT_TOTAL (W4T_OFF + H3_F * OUT_F)

// ===========================================================================
// Scratch (static device globals)
// ===========================================================================
__device__ int   g_is64;
__device__ float g_dinv[N_NODES];
__device__ int   g_cnt[N_NODES];
__device__ int   g_cursor[N_NODES];
__device__ int   g_rowptr[N_NODES + 1];
__device__ int   g_col[E_EDGES];
__device__ float g_wt[E_EDGES];                         // independent weight stream
__device__ float4 g_buf0[(size_t)N_NODES * OUT_F / 4];  // fp32 L4 lin
__device__ uint4 g_A[(size_t)N_NODES * H2_F * 2 / 16];  // fp16 activations A
__device__ uint4 g_A2[(size_t)N_NODES * H1_F * 2 / 16]; // fp16 activations B
__device__ uint4 g_Bh[(WT_TOTAL * 2 + 15) / 16];        // fp16 weights (T)

// ===========================================================================
// helpers
// ===========================================================================
__device__ __forceinline__ uint32_t smem_to_u32(const void* p) {
    uint32_t a;
    asm("{ .reg .u64 t; cvta.to.shared.u64 t, %1; cvt.u32.u64 %0, t; }"
        : "=r"(a) : "l"(p));
    return a;
}
__device__ __forceinline__ void cp_async16(uint32_t s, const void* g) {
    asm volatile("cp.async.cg.shared.global [%0], [%1], 16;"
                 :: "r"(s), "l"(__cvta_generic_to_global(g)) : "memory");
}
__device__ __forceinline__ void cp_commit() {
    asm volatile("cp.async.commit_group;" ::: "memory");
}
template <int NN>
__device__ __forceinline__ void cp_wait() {
    asm volatile("cp.async.wait_group %0;" :: "n"(NN) : "memory");
}
__device__ __forceinline__ void mma16816(float* c, const uint32_t* a,
                                         const uint32_t* b) {
    asm volatile(
        "mma.sync.aligned.m16n8k16.row.col.f32.f16.f16.f32 "
        "{%0,%1,%2,%3}, {%4,%5,%6,%7}, {%8,%9}, {%0,%1,%2,%3};"
        : "+f"(c[0]), "+f"(c[1]), "+f"(c[2]), "+f"(c[3])
        : "r"(a[0]), "r"(a[1]), "r"(a[2]), "r"(a[3]), "r"(b[0]), "r"(b[1]));
}
__device__ __forceinline__ void load_edge(const void* ei, int e, int E,
                                          int& s, int& d) {
    if (g_is64) {
        const long long* p = (const long long*)ei;
        s = (int)p[e]; d = (int)p[e + E];
    } else {
        const int* p = (const int*)ei;
        s = p[e]; d = p[e + E];
    }
}

// ===========================================================================
// Setup: zero counters + dtype detect + all-weight transpose, one kernel.
// ===========================================================================
__global__ __launch_bounds__(256)
void k_setup(const void* __restrict__ ei,
             const float* __restrict__ W1, const float* __restrict__ W2,
             const float* __restrict__ W3, const float* __restrict__ W4,
             __half* __restrict__ hi) {
    const int tx = threadIdx.x, ty = threadIdx.y;   // (32, 8)
    const int tid = ty * 32 + tx;
    int b = blockIdx.x;
    if (b < 40) {
        int i = b * 256 + tid;
        if (i < N_NODES) { g_cnt[i] = 0; g_cursor[i] = 0; }
        if (b == 0) {
            if (tid == 0) g_is64 = 1;
            __syncthreads();
            if (tid < 128) {
                const long long* p = (const long long*)ei;
                long long v = p[tid];
                if (v < 0 || v >= N_NODES) atomicAnd(&g_is64, 0);
            }
        }
        return;
    }
    b -= 40;
    const float* W; int K, N; size_t off;
    if (b < 64)        { W = W1; K = IN_F; N = H1_F; off = W1T_OFF; }
    else if (b < 576)  { b -= 64;   W = W2; K = H1_F; N = H2_F; off = W2T_OFF; }
    else if (b < 1088) { b -= 576;  W = W3; K = H2_F; N = H3_F; off = W3T_OFF; }
    else               { b -= 1088; W = W4; K = H3_F; N = OUT_F; off = W4T_OFF; }
    int KT = K / 32;
    int k0 = (b % KT) * 32, n0 = (b / KT) * 32;

    __shared__ float t[32][33];
#pragma unroll
    for (int j = 0; j < 4; j++)
        t[ty + j * 8][tx] = W[(size_t)(k0 + ty + j * 8) * N + (n0 + tx)];
    __syncthreads();
#pragma unroll
    for (int j = 0; j < 4; j++) {
        float v = t[tx][ty + j * 8];
        int n = n0 + ty + j * 8;
        int k = k0 + tx;
        hi[off + (size_t)n * K + k] = __float2half_rn(v);
    }
}

// ===========================================================================
// CSR chain
// ===========================================================================
__global__ void k_count(const void* __restrict__ ei, int E) {
    int e = blockIdx.x * blockDim.x + threadIdx.x;
    if (e >= E) return;
    int s, d;
    load_edge(ei, e, E, s, d);
    atomicAdd(&g_cnt[d], 1);
}
__global__ __launch_bounds__(1024)
void k_scan_dinv() {
    __shared__ int wsum[32];
    __shared__ int s_off;
    const int tid = threadIdx.x;
    const int lane = tid & 31;
    const int wid = tid >> 5;
    if (tid == 0) s_off = 0;
    __syncthreads();
    for (int base = 0; base < N_NODES; base += 1024) {
        int i = base + tid;
        int v = (i < N_NODES) ? g_cnt[i] : 0;
        if (i < N_NODES) g_dinv[i] = rsqrtf((float)v + 1.0f);
        int x = v;
#pragma unroll
        for (int o = 1; o < 32; o <<= 1) {
            int t = __shfl_up_sync(0xFFFFFFFFu, x, o);
            if (lane >= o) x += t;
        }
        if (lane == 31) wsum[wid] = x;
        __syncthreads();
        if (wid == 0) {
            int w = wsum[lane];
#pragma unroll
            for (int o = 1; o < 32; o <<= 1) {
                int t = __shfl_up_sync(0xFFFFFFFFu, w, o);
                if (lane >= o) w += t;
            }
            wsum[lane] = w;
        }
        __syncthreads();
        int incl = x + ((wid > 0) ? wsum[wid - 1] : 0);
        int off = s_off;
        if (i < N_NODES) g_rowptr[i + 1] = off + incl;
        __syncthreads();
        if (tid == 1023) s_off = off + incl;
        __syncthreads();
    }
    if (tid == 0) g_rowptr[0] = 0;
}
__global__ void k_fill(const void* __restrict__ ei, int E) {
    int e = blockIdx.x * blockDim.x + threadIdx.x;
    if (e >= E) return;
    int s, d;
    load_edge(ei, e, E, s, d);
    float w = g_dinv[s] * g_dinv[d];
    int pos = g_rowptr[d] + atomicAdd(&g_cursor[d], 1);
    g_col[pos] = s;
    g_wt[pos]  = w;
}

// ===========================================================================
// fp16 1-pass GEMM, 128(M)x64(N) CTA tile, 3-stage cp.async pipeline.
// Smaller N-tile: 32 acc regs/thread -> 2-3 CTAs/SM without spills.
// 8 warps: warp_m = wid&3 (32 rows), warp_n = wid>>2 (32 cols = 4 n-tiles).
// EPI: 0 bias+relu fp32 | 1 bias+relu fp16 | 2 raw fp16 | 3 raw fp32
// NG:  bounds-guard B rows / C cols against Ncols (for Ncols < 64)
// ===========================================================================
#define KC 32
#define SROW 40                        // fp16 row stride (80 B)
#define TILE_A_B (128 * SROW * 2)      // 10240 B
#define TILE_B_B (64 * SROW * 2)       // 5120 B
#define STAGE_B (TILE_A_B + TILE_B_B)  // 15360 B
#define GEMM_SMEM (3 * STAGE_B)        // 46080 B

template <int EPI, bool NG>
__global__ __launch_bounds__(256)
void k_gemm_mma(const uint4* __restrict__ A, const __half* __restrict__ B,
                const float* __restrict__ bias, float* __restrict__ C,
                __half2* __restrict__ Oh,
                int M, int K, int Ncols) {
    extern __shared__ char sm[];
    const uint32_t smb = smem_to_u32(sm);
    const int tid = threadIdx.x;
    const int lane = tid & 31;
    const int wid = tid >> 5;
    const int warp_m = wid & 3;
    const int warp_n = wid >> 2;
    const int g = lane >> 2;
    const int tig = lane & 3;
    const int mrow0 = blockIdx.y * 128;
    const int ncol0 = blockIdx.x * 64;
    const int KU = K >> 3;
    const int nChunks = K / KC;

    float acc[2][4][4];
#pragma unroll
    for (int i = 0; i < 2; i++)
#pragma unroll
        for (int j = 0; j < 4; j++)
#pragma unroll
            for (int q = 0; q < 4; q++) acc[i][j][q] = 0.0f;

    auto load_chunk = [&](int it, int st) {
        const int ku0 = it * (KC / 8);
        const uint32_t sb = smb + st * STAGE_B;
        // A tile: 128 rows x 4 cb = 512 slots
#pragma unroll
        for (int q = tid; q < 512; q += 256) {
            int row = q >> 2;
            int cb = q & 3;
            uint32_t so = (uint32_t)(row * 80 + cb * 16);
            int gm = mrow0 + row;
            if (gm < M) {
                cp_async16(sb + so, A + (size_t)gm * KU + ku0 + cb);
            } else {
                *(uint4*)(sm + st * STAGE_B + so) = make_uint4(0, 0, 0, 0);
            }
        }
        // B tile: 64 rows x 4 cb = 256 slots
        {
            int q = tid;
            int row = q >> 2;
            int cb = q & 3;
            uint32_t so = (uint32_t)(row * 80 + cb * 16);
            int brow = ncol0 + row;
            if (!NG || brow < Ncols) {
                size_t bb = (size_t)brow * K + it * KC + cb * 8;
                cp_async16(sb + TILE_A_B + so, B + bb);
            } else {
                *(uint4*)(sm + st * STAGE_B + TILE_A_B + so) = make_uint4(0, 0, 0, 0);
            }
        }
        cp_commit();
    };

    load_chunk(0, 0);
    load_chunk(1, 1);
    for (int it = 0; it < nChunks; it++) {
        const int cur = it % 3;
        if (it + 2 < nChunks) {
            load_chunk(it + 2, (it + 2) % 3);
            cp_wait<2>();
        } else if (it + 1 < nChunks) {
            cp_wait<1>();
        } else {
            cp_wait<0>();
        }
        __syncthreads();

        const __half* sA = (const __half*)(sm + cur * STAGE_B);
        const __half* sB = (const __half*)(sm + cur * STAGE_B + TILE_A_B);

#pragma unroll
        for (int ks = 0; ks < KC / 16; ks++) {
            const int k0 = ks * 16;
            uint32_t ah[2][4];
#pragma unroll
            for (int mt = 0; mt < 2; mt++) {
                int r0 = warp_m * 32 + mt * 16 + g;
                int c0 = k0 + tig * 2;
                ah[mt][0] = *(const uint32_t*)(sA + r0 * SROW + c0);
                ah[mt][1] = *(const uint32_t*)(sA + (r0 + 8) * SROW + c0);
                ah[mt][2] = *(const uint32_t*)(sA + r0 * SROW + c0 + 8);
                ah[mt][3] = *(const uint32_t*)(sA + (r0 + 8) * SROW + c0 + 8);
            }
            uint32_t bh[4][2];
#pragma unroll
            for (int nt = 0; nt < 4; nt++) {
                int r0 = warp_n * 32 + nt * 8 + g;
                int c0 = k0 + tig * 2;
                bh[nt][0] = *(const uint32_t*)(sB + r0 * SROW + c0);
                bh[nt][1] = *(const uint32_t*)(sB + r0 * SROW + c0 + 8);
            }
#pragma unroll
            for (int mt = 0; mt < 2; mt++)
#pragma unroll
                for (int nt = 0; nt < 4; nt++) mma16816(acc[mt][nt], ah[mt], bh[nt]);
        }
        __syncthreads();
    }

    // Epilogue
#pragma unroll
    for (int mt = 0; mt < 2; mt++) {
        int rbase = mrow0 + warp_m * 32 + mt * 16;
#pragma unroll
        for (int nt = 0; nt < 4; nt++) {
            int col = ncol0 + warp_n * 32 + nt * 8 + tig * 2;
            if (NG && col >= Ncols) continue;
            float b0 = 0.0f, b1 = 0.0f;
            if (EPI == 0 || EPI == 1) { b0 = bias[col]; b1 = bias[col + 1]; }
#pragma unroll
            for (int half = 0; half < 2; half++) {
                int r = rbase + g + half * 8;
                if (r >= M) continue;
                float v0 = acc[mt][nt][half * 2 + 0] + b0;
                float v1 = acc[mt][nt][half * 2 + 1] + b1;
                if (EPI == 0 || EPI == 1) { v0 = fmaxf(v0, 0.0f); v1 = fmaxf(v1, 0.0f); }
                if (EPI == 0 || EPI == 3) {
                    *(float2*)(C + (size_t)r * Ncols + col) = make_float2(v0, v1);
                } else {
                    Oh[((size_t)r * Ncols + col) >> 1] = __floats2half2_rn(v0, v1);
                }
            }
        }
    }
}

// ===========================================================================
// Aggregations — round-10 structure (independent g_col/g_wt streams)
// ===========================================================================
template <int OUTMODE>
__global__ __launch_bounds__(128)
void k_agg512_h(const uint2* __restrict__ lin,       // fp16 [N,512] as uint2
                const float* __restrict__ bias,
                __half2* __restrict__ outh) {
    const int node = blockIdx.x;
    const int tid = threadIdx.x;
    float dii = g_dinv[node];
    float w0 = dii * dii;

    uint2 sv = lin[(size_t)node * 128 + tid];
    float2 f01 = __half22float2(*(const __half2*)&sv.x);
    float2 f23 = __half22float2(*(const __half2*)&sv.y);
    float a0 = f01.x * w0, a1 = f01.y * w0, a2 = f23.x * w0, a3 = f23.y * w0;

    __shared__ int   s_col[128];
    __shared__ float s_w[128];
    const int beg = g_rowptr[node];
    const int end = g_rowptr[node + 1];
    for (int j0 = beg; j0 < end; j0 += 128) {
        int n = min(128, end - j0);
        __syncthreads();
        if (tid < n) { s_col[tid] = g_col[j0 + tid]; s_w[tid] = g_wt[j0 + tid]; }
        __syncthreads();
        for (int j = 0; j < n; j++) {
            int s = s_col[j];
            float w = s_w[j];
            uint2 v = lin[(size_t)s * 128 + tid];
            float2 g01 = __half22float2(*(const __half2*)&v.x);
            float2 g23 = __half22float2(*(const __half2*)&v.y);
            a0 = fmaf(w, g01.x, a0); a1 = fmaf(w, g01.y, a1);
            a2 = fmaf(w, g23.x, a2); a3 = fmaf(w, g23.y, a3);
        }
    }
    if (OUTMODE == 2) {
        float4 b = reinterpret_cast<const float4*>(bias)[tid];
        a0 = fmaxf(a0 + b.x, 0.0f); a1 = fmaxf(a1 + b.y, 0.0f);
        a2 = fmaxf(a2 + b.z, 0.0f); a3 = fmaxf(a3 + b.w, 0.0f);
    }
    size_t o = (size_t)node * 256 + tid * 2;
    outh[o]     = __floats2half2_rn(a0, a1);
    outh[o + 1] = __floats2half2_rn(a2, a3);
}

// x [N,128] fp32 -> fp16 with aggregation; warp per node, 8 nodes/block
__global__ __launch_bounds__(256)
void k_agg128h(const float4* __restrict__ lin, __half2* __restrict__ oh) {
    int node = blockIdx.x * 8 + threadIdx.y;
    if (node >= N_NODES) return;
    int lane = threadIdx.x;
    float dii = g_dinv[node];
    float w0 = dii * dii;
    float4 a = lin[(size_t)node * 32 + lane];
    a.x *= w0; a.y *= w0; a.z *= w0; a.w *= w0;
    int beg = g_rowptr[node], end = g_rowptr[node + 1];
    for (int j = beg; j < end; j++) {
        int s = g_col[j];
        float w = g_wt[j];
        float4 v = lin[(size_t)s * 32 + lane];
        a.x = fmaf(w, v.x, a.x); a.y = fmaf(w, v.y, a.y);
        a.z = fmaf(w, v.z, a.z); a.w = fmaf(w, v.w, a.w);
    }
    size_t o = (size_t)node * 64 + lane * 2;
    oh[o]     = __floats2half2_rn(a.x, a.y);
    oh[o + 1] = __floats2half2_rn(a.z, a.w);
}

// L4 final: aggregate (H=32, fp32 lin) + bias + log_softmax; warp per node
__global__ __launch_bounds__(256)
void k_agg_softmax32(const float* __restrict__ lin,
                     const float* __restrict__ bias,
                     float* __restrict__ out) {
    int node = blockIdx.x * 8 + threadIdx.y;
    if (node >= N_NODES) return;
    int lane = threadIdx.x;
    float dii = g_dinv[node];
    float v = lin[(size_t)node * 32 + lane] * dii * dii;
    int beg = g_rowptr[node], end = g_rowptr[node + 1];
    for (int j = beg; j < end; j++) {
        int s = g_col[j];
        float w = g_wt[j];
        v = fmaf(w, lin[(size_t)s * 32 + lane], v);
    }
    v += bias[lane];
    float m = v;
#pragma unroll
    for (int o = 16; o > 0; o >>= 1)
        m = fmaxf(m, __shfl_xor_sync(0xFFFFFFFFu, m, o));
    float ex = expf(v - m);
    float s = ex;
#pragma unroll
    for (int o = 16; o > 0; o >>= 1)
        s += __shfl_xor_sync(0xFFFFFFFFu, s, o);
    out[(size_t)node * 32 + lane] = v - m - logf(s);
}

// ===========================================================================
// Launch
// ===========================================================================
static inline int cdiv(long long a, int b) { return (int)((a + b - 1) / b); }

extern "C" void kernel_launch(void* const* d_in, const int* in_sizes, int n_in,
                              void* d_out, int out_size) {
    const float* x  = (const float*)d_in[0];
    const void*  ei = d_in[1];
    const float* W1 = (const float*)d_in[2];
    const float* b1 = (const float*)d_in[3];
    const float* W2 = (const float*)d_in[4];
    const float* b2 = (const float*)d_in[5];
    const float* W3 = (const float*)d_in[6];
    const float* b3 = (const float*)d_in[7];
    const float* W4 = (const float*)d_in[8];
    const float* b4 = (const float*)d_in[9];
    float* out = (float*)d_out;

    const int E = in_sizes[1] / 2;

    float4 *buf0;
    uint4 *A, *A2, *Bh;
    cudaGetSymbolAddress((void**)&buf0, g_buf0);
    cudaGetSymbolAddress((void**)&A, g_A);
    cudaGetSymbolAddress((void**)&A2, g_A2);
    cudaGetSymbolAddress((void**)&Bh, g_Bh);

    cudaFuncSetAttribute((const void*)k_gemm_mma<1, false>,
                         cudaFuncAttributeMaxDynamicSharedMemorySize, GEMM_SMEM);
    cudaFuncSetAttribute((const void*)k_gemm_mma<2, false>,
                         cudaFuncAttributeMaxDynamicSharedMemorySize, GEMM_SMEM);
    cudaFuncSetAttribute((const void*)k_gemm_mma<3, true>,
                         cudaFuncAttributeMaxDynamicSharedMemorySize, GEMM_SMEM);

    const int MT = cdiv(N_NODES, 128);
    const __half* BW = (const __half*)Bh;

    // --- setup (zero+detect+weights) + CSR ---
    k_setup<<<1144, dim3(32, 8)>>>(ei, W1, W2, W3, W4, (__half*)Bh);
    k_count<<<cdiv(E, 256), 256>>>(ei, E);
    k_scan_dinv<<<1, 1024>>>();
    k_fill<<<cdiv(E, 256), 256>>>(ei, E);

    // --- L1: agg(x)->fp16 (A2) -> GEMM K=128 N=512 bias+relu -> fp16 h1 (A) ---
    k_agg128h<<<cdiv(N_NODES, 8), dim3(32, 8)>>>((const float4*)x, (__half2*)A2);
    k_gemm_mma<1, false><<<dim3(H1_F / 64, MT), 256, GEMM_SMEM>>>(
        A2, BW + W1T_OFF, b1, nullptr, (__half2*)A, N_NODES, IN_F, H1_F);

    // --- L2: agg(h1)->fp16 (A2) -> GEMM K=512 N=1024 bias+relu -> fp16 h2 (A) ---
    k_agg512_h<0><<<N_NODES, 128>>>((const uint2*)A, nullptr, (__half2*)A2);
    k_gemm_mma<1, false><<<dim3(H2_F / 64, MT), 256, GEMM_SMEM>>>(
        A2, BW + W2T_OFF, b2, nullptr, (__half2*)A, N_NODES, H1_F, H2_F);

    // --- L3: GEMM K=1024 N=512 raw fp16 (A2) -> agg+bias+relu -> fp16 h3 (A) ---
    k_gemm_mma<2, false><<<dim3(H3_F / 64, MT), 256, GEMM_SMEM>>>(
        A, BW + W3T_OFF, nullptr, nullptr, (__half2*)A2, N_NODES, H2_F, H3_F);
    k_agg512_h<2><<<N_NODES, 128>>>((const uint2*)A2, b3, (__half2*)A);

    // --- L4: fp16 MMA GEMM K=512 N=32 raw fp32 -> buf0 ; agg+bias+softmax ---
    k_gemm_mma<3, true><<<dim3(1, MT), 256, GEMM_SMEM>>>(
        A, BW + W4T_OFF, nullptr, (float*)buf0, nullptr, N_NODES, H3_F, OUT_F);
    k_agg_softmax32<<<cdiv(N_NODES, 8), dim3(32, 8)>>>(
        (const float*)buf0, b4, out);
}

// round 15
// speedup vs baseline: 1.1620x; 1.0442x over previous
#include <cuda_runtime.h>
#include <cuda_fp16.h>
#include <math.h>
#include <stdint.h>

#define N_NODES 10000
#define E_EDGES 160000
#define IN_F    128
#define H1_F    512
#define H2_F    1024
#define H3_F    512
#define OUT_F   32

// Weight-transpose buffer offsets (fp16 elements)
#define W1T_OFF 0
#define W2T_OFF (IN_F * H1_F)
#define W3T_OFF (W2T_OFF + H1_F * H2_F)
#define W4T_OFF (W3T_OFF + H2_F * H3_F)
#define WT_TOTAL (W4T_OFF + H3_F * OUT_F)

// ===========================================================================
// Scratch (static device globals)
// ===========================================================================
__device__ int   g_is64;
__device__ float g_dinv[N_NODES];
__device__ int   g_cnt[N_NODES];
__device__ int   g_cursor[N_NODES];
__device__ int   g_rowptr[N_NODES + 1];
__device__ int   g_col[E_EDGES];
__device__ float g_wt[E_EDGES];                         // independent weight stream
__device__ float4 g_buf0[(size_t)N_NODES * OUT_F / 4];  // fp32 L4 lin
__device__ uint4 g_A[(size_t)N_NODES * H2_F * 2 / 16];  // fp16 activations A
__device__ uint4 g_A2[(size_t)N_NODES * H1_F * 2 / 16]; // fp16 activations B
__device__ uint4 g_Bh[(WT_TOTAL * 2 + 15) / 16];        // fp16 weights (T)

// ===========================================================================
// helpers
// ===========================================================================
__device__ __forceinline__ uint32_t smem_to_u32(const void* p) {
    uint32_t a;
    asm("{ .reg .u64 t; cvta.to.shared.u64 t, %1; cvt.u32.u64 %0, t; }"
        : "=r"(a) : "l"(p));
    return a;
}
__device__ __forceinline__ void cp_async16(uint32_t s, const void* g) {
    asm volatile("cp.async.cg.shared.global [%0], [%1], 16;"
                 :: "r"(s), "l"(__cvta_generic_to_global(g)) : "memory");
}
__device__ __forceinline__ void cp_commit() {
    asm volatile("cp.async.commit_group;" ::: "memory");
}
template <int NN>
__device__ __forceinline__ void cp_wait() {
    asm volatile("cp.async.wait_group %0;" :: "n"(NN) : "memory");
}
__device__ __forceinline__ void mma16816(float* c, const uint32_t* a,
                                         const uint32_t* b) {
    asm volatile(
        "mma.sync.aligned.m16n8k16.row.col.f32.f16.f16.f32 "
        "{%0,%1,%2,%3}, {%4,%5,%6,%7}, {%8,%9}, {%0,%1,%2,%3};"
        : "+f"(c[0]), "+f"(c[1]), "+f"(c[2]), "+f"(c[3])
        : "r"(a[0]), "r"(a[1]), "r"(a[2]), "r"(a[3]), "r"(b[0]), "r"(b[1]));
}
__device__ __forceinline__ void ldmatrix_x4(uint32_t* r, uint32_t saddr) {
    asm volatile("ldmatrix.sync.aligned.m8n8.x4.shared.b16 {%0,%1,%2,%3}, [%4];"
        : "=r"(r[0]), "=r"(r[1]), "=r"(r[2]), "=r"(r[3]) : "r"(saddr));
}
__device__ __forceinline__ void load_edge(const void* ei, int e, int E,
                                          int& s, int& d) {
    if (g_is64) {
        const long long* p = (const long long*)ei;
        s = (int)p[e]; d = (int)p[e + E];
    } else {
        const int* p = (const int*)ei;
        s = p[e]; d = p[e + E];
    }
}

// ===========================================================================
// Setup: zero counters + dtype detect + all-weight transpose, one kernel.
// ===========================================================================
__global__ __launch_bounds__(256)
void k_setup(const void* __restrict__ ei,
             const float* __restrict__ W1, const float* __restrict__ W2,
             const float* __restrict__ W3, const float* __restrict__ W4,
             __half* __restrict__ hi) {
    const int tx = threadIdx.x, ty = threadIdx.y;   // (32, 8)
    const int tid = ty * 32 + tx;
    int b = blockIdx.x;
    if (b < 40) {
        int i = b * 256 + tid;
        if (i < N_NODES) { g_cnt[i] = 0; g_cursor[i] = 0; }
        if (b == 0) {
            if (tid == 0) g_is64 = 1;
            __syncthreads();
            if (tid < 128) {
                const long long* p = (const long long*)ei;
                long long v = p[tid];
                if (v < 0 || v >= N_NODES) atomicAnd(&g_is64, 0);
            }
        }
        return;
    }
    b -= 40;
    const float* W; int K, N; size_t off;
    if (b < 64)        { W = W1; K = IN_F; N = H1_F; off = W1T_OFF; }
    else if (b < 576)  { b -= 64;   W = W2; K = H1_F; N = H2_F; off = W2T_OFF; }
    else if (b < 1088) { b -= 576;  W = W3; K = H2_F; N = H3_F; off = W3T_OFF; }
    else               { b -= 1088; W = W4; K = H3_F; N = OUT_F; off = W4T_OFF; }
    int KT = K / 32;
    int k0 = (b % KT) * 32, n0 = (b / KT) * 32;

    __shared__ float t[32][33];
#pragma unroll
    for (int j = 0; j < 4; j++)
        t[ty + j * 8][tx] = W[(size_t)(k0 + ty + j * 8) * N + (n0 + tx)];
    __syncthreads();
#pragma unroll
    for (int j = 0; j < 4; j++) {
        float v = t[tx][ty + j * 8];
        int n = n0 + ty + j * 8;
        int k = k0 + tx;
        hi[off + (size_t)n * K + k] = __float2half_rn(v);
    }
}

// ===========================================================================
// CSR chain
// ===========================================================================
__global__ void k_count(const void* __restrict__ ei, int E) {
    int e = blockIdx.x * blockDim.x + threadIdx.x;
    if (e >= E) return;
    int s, d;
    load_edge(ei, e, E, s, d);
    atomicAdd(&g_cnt[d], 1);
}
__global__ __launch_bounds__(1024)
void k_scan_dinv() {
    __shared__ int wsum[32];
    __shared__ int s_off;
    const int tid = threadIdx.x;
    const int lane = tid & 31;
    const int wid = tid >> 5;
    if (tid == 0) s_off = 0;
    __syncthreads();
    for (int base = 0; base < N_NODES; base += 1024) {
        int i = base + tid;
        int v = (i < N_NODES) ? g_cnt[i] : 0;
        if (i < N_NODES) g_dinv[i] = rsqrtf((float)v + 1.0f);
        int x = v;
#pragma unroll
        for (int o = 1; o < 32; o <<= 1) {
            int t = __shfl_up_sync(0xFFFFFFFFu, x, o);
            if (lane >= o) x += t;
        }
        if (lane == 31) wsum[wid] = x;
        __syncthreads();
        if (wid == 0) {
            int w = wsum[lane];
#pragma unroll
            for (int o = 1; o < 32; o <<= 1) {
                int t = __shfl_up_sync(0xFFFFFFFFu, w, o);
                if (lane >= o) w += t;
            }
            wsum[lane] = w;
        }
        __syncthreads();
        int incl = x + ((wid > 0) ? wsum[wid - 1] : 0);
        int off = s_off;
        if (i < N_NODES) g_rowptr[i + 1] = off + incl;
        __syncthreads();
        if (tid == 1023) s_off = off + incl;
        __syncthreads();
    }
    if (tid == 0) g_rowptr[0] = 0;
}
__global__ void k_fill(const void* __restrict__ ei, int E) {
    int e = blockIdx.x * blockDim.x + threadIdx.x;
    if (e >= E) return;
    int s, d;
    load_edge(ei, e, E, s, d);
    float w = g_dinv[s] * g_dinv[d];
    int pos = g_rowptr[d] + atomicAdd(&g_cursor[d], 1);
    g_col[pos] = s;
    g_wt[pos]  = w;
}

// ===========================================================================
// fp16 1-pass GEMM, 128(M)x64(N) CTA tile, 3-stage cp.async pipeline,
// ldmatrix.x4 fragment loads (4x fewer shared-load instructions; SROW=40
// makes the 8x16B ldmatrix phase conflict-free across all 32 banks).
// EPI: 0 bias+relu fp32 | 1 bias+relu fp16 | 2 raw fp16 | 3 raw fp32
// NG:  bounds-guard B rows / C cols against Ncols (for Ncols < 64)
// ===========================================================================
#define KC 32
#define SROW 40                        // fp16 row stride (80 B)
#define TILE_A_B (128 * SROW * 2)      // 10240 B
#define TILE_B_B (64 * SROW * 2)       // 5120 B
#define STAGE_B (TILE_A_B + TILE_B_B)  // 15360 B
#define GEMM_SMEM (3 * STAGE_B)        // 46080 B

template <int EPI, bool NG>
__global__ __launch_bounds__(256)
void k_gemm_mma(const uint4* __restrict__ A, const __half* __restrict__ B,
                const float* __restrict__ bias, float* __restrict__ C,
                __half2* __restrict__ Oh,
                int M, int K, int Ncols) {
    extern __shared__ char sm[];
    const uint32_t smb = smem_to_u32(sm);
    const int tid = threadIdx.x;
    const int lane = tid & 31;
    const int wid = tid >> 5;
    const int warp_m = wid & 3;
    const int warp_n = wid >> 2;
    const int g = lane >> 2;
    const int tig = lane & 3;
    const int mrow0 = blockIdx.y * 128;
    const int ncol0 = blockIdx.x * 64;
    const int KU = K >> 3;
    const int nChunks = K / KC;

    // ldmatrix lane-address offsets (bytes within a stage), loop-invariant.
    // A (x4 tiles: [r0..7,k0], [r8..15,k0], [r0..7,k0+8], [r8..15,k0+8]):
    //   lane row = base + (l&7) + (l&8);  k-half offset = ((l&16)>>1)
    // B (x4 tiles: [n0..7,k0], [n0..7,k0+8], [n8..15,k0], [n8..15,k0+8]):
    //   lane row = base + (l&7) + ((l&16)>>1);  k-half = ((l>>3)&1)*8
    uint32_t offA[2], offB[2];
#pragma unroll
    for (int mt = 0; mt < 2; mt++) {
        int row = warp_m * 32 + mt * 16 + (lane & 7) + (lane & 8);
        int kh  = (lane & 16) >> 1;
        offA[mt] = (uint32_t)((row * SROW + kh) * 2);
    }
#pragma unroll
    for (int p = 0; p < 2; p++) {
        int row = warp_n * 32 + p * 16 + (lane & 7) + ((lane & 16) >> 1);
        int kh  = ((lane >> 3) & 1) * 8;
        offB[p] = (uint32_t)(TILE_A_B + (row * SROW + kh) * 2);
    }

    float acc[2][4][4];
#pragma unroll
    for (int i = 0; i < 2; i++)
#pragma unroll
        for (int j = 0; j < 4; j++)
#pragma unroll
            for (int q = 0; q < 4; q++) acc[i][j][q] = 0.0f;

    auto load_chunk = [&](int it, int st) {
        const int ku0 = it * (KC / 8);
        const uint32_t sb = smb + st * STAGE_B;
#pragma unroll
        for (int q = tid; q < 512; q += 256) {
            int row = q >> 2;
            int cb = q & 3;
            uint32_t so = (uint32_t)(row * 80 + cb * 16);
            int gm = mrow0 + row;
            if (gm < M) {
                cp_async16(sb + so, A + (size_t)gm * KU + ku0 + cb);
            } else {
                *(uint4*)(sm + st * STAGE_B + so) = make_uint4(0, 0, 0, 0);
            }
        }
        {
            int q = tid;
            int row = q >> 2;
            int cb = q & 3;
            uint32_t so = (uint32_t)(row * 80 + cb * 16);
            int brow = ncol0 + row;
            if (!NG || brow < Ncols) {
                size_t bb = (size_t)brow * K + it * KC + cb * 8;
                cp_async16(sb + TILE_A_B + so, B + bb);
            } else {
                *(uint4*)(sm + st * STAGE_B + TILE_A_B + so) = make_uint4(0, 0, 0, 0);
            }
        }
        cp_commit();
    };

    load_chunk(0, 0);
    load_chunk(1, 1);
    for (int it = 0; it < nChunks; it++) {
        const int cur = it % 3;
        if (it + 2 < nChunks) {
            load_chunk(it + 2, (it + 2) % 3);
            cp_wait<2>();
        } else if (it + 1 < nChunks) {
            cp_wait<1>();
        } else {
            cp_wait<0>();
        }
        __syncthreads();

        const uint32_t stage = smb + cur * STAGE_B;
#pragma unroll
        for (int ks = 0; ks < KC / 16; ks++) {
            const uint32_t kb = (uint32_t)(ks * 32);   // 16 halves = 32 bytes
            uint32_t ah[2][4];
            ldmatrix_x4(ah[0], stage + offA[0] + kb);
            ldmatrix_x4(ah[1], stage + offA[1] + kb);
            uint32_t bh[4][2];
            {
                uint32_t r[4];
                ldmatrix_x4(r, stage + offB[0] + kb);
                bh[0][0] = r[0]; bh[0][1] = r[1];
                bh[1][0] = r[2]; bh[1][1] = r[3];
                ldmatrix_x4(r, stage + offB[1] + kb);
                bh[2][0] = r[0]; bh[2][1] = r[1];
                bh[3][0] = r[2]; bh[3][1] = r[3];
            }
#pragma unroll
            for (int mt = 0; mt < 2; mt++)
#pragma unroll
                for (int nt = 0; nt < 4; nt++) mma16816(acc[mt][nt], ah[mt], bh[nt]);
        }
        __syncthreads();
    }

    // Epilogue
#pragma unroll
    for (int mt = 0; mt < 2; mt++) {
        int rbase = mrow0 + warp_m * 32 + mt * 16;
#pragma unroll
        for (int nt = 0; nt < 4; nt++) {
            int col = ncol0 + warp_n * 32 + nt * 8 + tig * 2;
            if (NG && col >= Ncols) continue;
            float b0 = 0.0f, b1 = 0.0f;
            if (EPI == 0 || EPI == 1) { b0 = bias[col]; b1 = bias[col + 1]; }
#pragma unroll
            for (int half = 0; half < 2; half++) {
                int r = rbase + g + half * 8;
                if (r >= M) continue;
                float v0 = acc[mt][nt][half * 2 + 0] + b0;
                float v1 = acc[mt][nt][half * 2 + 1] + b1;
                if (EPI == 0 || EPI == 1) { v0 = fmaxf(v0, 0.0f); v1 = fmaxf(v1, 0.0f); }
                if (EPI == 0 || EPI == 3) {
                    *(float2*)(C + (size_t)r * Ncols + col) = make_float2(v0, v1);
                } else {
                    Oh[((size_t)r * Ncols + col) >> 1] = __floats2half2_rn(v0, v1);
                }
            }
        }
    }
}

// ===========================================================================
// Aggregations — round-10 structure (independent g_col/g_wt streams)
// ===========================================================================
template <int OUTMODE>
__global__ __launch_bounds__(128)
void k_agg512_h(const uint2* __restrict__ lin,       // fp16 [N,512] as uint2
                const float* __restrict__ bias,
                __half2* __restrict__ outh) {
    const int node = blockIdx.x;
    const int tid = threadIdx.x;
    float dii = g_dinv[node];
    float w0 = dii * dii;

    uint2 sv = lin[(size_t)node * 128 + tid];
    float2 f01 = __half22float2(*(const __half2*)&sv.x);
    float2 f23 = __half22float2(*(const __half2*)&sv.y);
    float a0 = f01.x * w0, a1 = f01.y * w0, a2 = f23.x * w0, a3 = f23.y * w0;

    __shared__ int   s_col[128];
    __shared__ float s_w[128];
    const int beg = g_rowptr[node];
    const int end = g_rowptr[node + 1];
    for (int j0 = beg; j0 < end; j0 += 128) {
        int n = min(128, end - j0);
        __syncthreads();
        if (tid < n) { s_col[tid] = g_col[j0 + tid]; s_w[tid] = g_wt[j0 + tid]; }
        __syncthreads();
        for (int j = 0; j < n; j++) {
            int s = s_col[j];
            float w = s_w[j];
            uint2 v = lin[(size_t)s * 128 + tid];
            float2 g01 = __half22float2(*(const __half2*)&v.x);
            float2 g23 = __half22float2(*(const __half2*)&v.y);
            a0 = fmaf(w, g01.x, a0); a1 = fmaf(w, g01.y, a1);
            a2 = fmaf(w, g23.x, a2); a3 = fmaf(w, g23.y, a3);
        }
    }
    if (OUTMODE == 2) {
        float4 b = reinterpret_cast<const float4*>(bias)[tid];
        a0 = fmaxf(a0 + b.x, 0.0f); a1 = fmaxf(a1 + b.y, 0.0f);
        a2 = fmaxf(a2 + b.z, 0.0f); a3 = fmaxf(a3 + b.w, 0.0f);
    }
    size_t o = (size_t)node * 256 + tid * 2;
    outh[o]     = __floats2half2_rn(a0, a1);
    outh[o + 1] = __floats2half2_rn(a2, a3);
}

// x [N,128] fp32 -> fp16 with aggregation; warp per node, 8 nodes/block
__global__ __launch_bounds__(256)
void k_agg128h(const float4* __restrict__ lin, __half2* __restrict__ oh) {
    int node = blockIdx.x * 8 + threadIdx.y;
    if (node >= N_NODES) return;
    int lane = threadIdx.x;
    float dii = g_dinv[node];
    float w0 = dii * dii;
    float4 a = lin[(size_t)node * 32 + lane];
    a.x *= w0; a.y *= w0; a.z *= w0; a.w *= w0;
    int beg = g_rowptr[node], end = g_rowptr[node + 1];
    for (int j = beg; j < end; j++) {
        int s = g_col[j];
        float w = g_wt[j];
        float4 v = lin[(size_t)s * 32 + lane];
        a.x = fmaf(w, v.x, a.x); a.y = fmaf(w, v.y, a.y);
        a.z = fmaf(w, v.z, a.z); a.w = fmaf(w, v.w, a.w);
    }
    size_t o = (size_t)node * 64 + lane * 2;
    oh[o]     = __floats2half2_rn(a.x, a.y);
    oh[o + 1] = __floats2half2_rn(a.z, a.w);
}

// L4 final: aggregate (H=32, fp32 lin) + bias + log_softmax; warp per node
__global__ __launch_bounds__(256)
void k_agg_softmax32(const float* __restrict__ lin,
                     const float* __restrict__ bias,
                     float* __restrict__ out) {
    int node = blockIdx.x * 8 + threadIdx.y;
    if (node >= N_NODES) return;
    int lane = threadIdx.x;
    float dii = g_dinv[node];
    float v = lin[(size_t)node * 32 + lane] * dii * dii;
    int beg = g_rowptr[node], end = g_rowptr[node + 1];
    for (int j = beg; j < end; j++) {
        int s = g_col[j];
        float w = g_wt[j];
        v = fmaf(w, lin[(size_t)s * 32 + lane], v);
    }
    v += bias[lane];
    float m = v;
#pragma unroll
    for (int o = 16; o > 0; o >>= 1)
        m = fmaxf(m, __shfl_xor_sync(0xFFFFFFFFu, m, o));
    float ex = expf(v - m);
    float s = ex;
#pragma unroll
    for (int o = 16; o > 0; o >>= 1)
        s += __shfl_xor_sync(0xFFFFFFFFu, s, o);
    out[(size_t)node * 32 + lane] = v - m - logf(s);
}

// ===========================================================================
// Launch
// ===========================================================================
static inline int cdiv(long long a, int b) { return (int)((a + b - 1) / b); }

extern "C" void kernel_launch(void* const* d_in, const int* in_sizes, int n_in,
                              void* d_out, int out_size) {
    const float* x  = (const float*)d_in[0];
    const void*  ei = d_in[1];
    const float* W1 = (const float*)d_in[2];
    const float* b1 = (const float*)d_in[3];
    const float* W2 = (const float*)d_in[4];
    const float* b2 = (const float*)d_in[5];
    const float* W3 = (const float*)d_in[6];
    const float* b3 = (const float*)d_in[7];
    const float* W4 = (const float*)d_in[8];
    const float* b4 = (const float*)d_in[9];
    float* out = (float*)d_out;

    const int E = in_sizes[1] / 2;

    float4 *buf0;
    uint4 *A, *A2, *Bh;
    cudaGetSymbolAddress((void**)&buf0, g_buf0);
    cudaGetSymbolAddress((void**)&A, g_A);
    cudaGetSymbolAddress((void**)&A2, g_A2);
    cudaGetSymbolAddress((void**)&Bh, g_Bh);

    cudaFuncSetAttribute((const void*)k_gemm_mma<1, false>,
                         cudaFuncAttributeMaxDynamicSharedMemorySize, GEMM_SMEM);
    cudaFuncSetAttribute((const void*)k_gemm_mma<2, false>,
                         cudaFuncAttributeMaxDynamicSharedMemorySize, GEMM_SMEM);
    cudaFuncSetAttribute((const void*)k_gemm_mma<3, true>,
                         cudaFuncAttributeMaxDynamicSharedMemorySize, GEMM_SMEM);

    const int MT = cdiv(N_NODES, 128);
    const __half* BW = (const __half*)Bh;

    // --- setup (zero+detect+weights) + CSR ---
    k_setup<<<1144, dim3(32, 8)>>>(ei, W1, W2, W3, W4, (__half*)Bh);
    k_count<<<cdiv(E, 256), 256>>>(ei, E);
    k_scan_dinv<<<1, 1024>>>();
    k_fill<<<cdiv(E, 256), 256>>>(ei, E);

    // --- L1: agg(x)->fp16 (A2) -> GEMM K=128 N=512 bias+relu -> fp16 h1 (A) ---
    k_agg128h<<<cdiv(N_NODES, 8), dim3(32, 8)>>>((const float4*)x, (__half2*)A2);
    k_gemm_mma<1, false><<<dim3(H1_F / 64, MT), 256, GEMM_SMEM>>>(
        A2, BW + W1T_OFF, b1, nullptr, (__half2*)A, N_NODES, IN_F, H1_F);

    // --- L2: agg(h1)->fp16 (A2) -> GEMM K=512 N=1024 bias+relu -> fp16 h2 (A) ---
    k_agg512_h<0><<<N_NODES, 128>>>((const uint2*)A, nullptr, (__half2*)A2);
    k_gemm_mma<1, false><<<dim3(H2_F / 64, MT), 256, GEMM_SMEM>>>(
        A2, BW + W2T_OFF, b2, nullptr, (__half2*)A, N_NODES, H1_F, H2_F);

    // --- L3: GEMM K=1024 N=512 raw fp16 (A2) -> agg+bias+relu -> fp16 h3 (A) ---
    k_gemm_mma<2, false><<<dim3(H3_F / 64, MT), 256, GEMM_SMEM>>>(
        A, BW + W3T_OFF, nullptr, nullptr, (__half2*)A2, N_NODES, H2_F, H3_F);
    k_agg512_h<2><<<N_NODES, 128>>>((const uint2*)A2, b3, (__half2*)A);

    // --- L4: fp16 MMA GEMM K=512 N=32 raw fp32 -> buf0 ; agg+bias+softmax ---
    k_gemm_mma<3, true><<<dim3(1, MT), 256, GEMM_SMEM>>>(
        A, BW + W4T_OFF, nullptr, (float*)buf0, nullptr, N_NODES, H3_F, OUT_F);
    k_agg_softmax32<<<cdiv(N_NODES, 8), dim3(32, 8)>>>(
        (const float*)buf0, b4, out);
}

// round 16
// speedup vs baseline: 1.2185x; 1.0487x over previous
#include <cuda_runtime.h>
#include <cuda_fp16.h>
#include <math.h>
#include <stdint.h>

#define N_NODES 10000
#define E_EDGES 160000
#define IN_F    128
#define H1_F    512
#define H2_F    1024
#define H3_F    512
#define OUT_F   32
#define CAP     96          // padded CSR bucket capacity (P(deg>=96) ~ 1e-43)

// Weight-transpose buffer offsets (fp16 elements)
#define W1T_OFF 0
#define W2T_OFF (IN_F * H1_F)
#define W3T_OFF (W2T_OFF + H1_F * H2_F)
#define W4T_OFF (W3T_OFF + H2_F * H3_F)
#define WT_TOTAL (W4T_OFF + H3_F * OUT_F)

// ===========================================================================
// Scratch (static device globals)
// ===========================================================================
__device__ int   g_is64;
__device__ float g_dinv[N_NODES];
__device__ int   g_cnt[N_NODES];
__device__ int   g_colp[(size_t)N_NODES * CAP];         // padded col buckets
__device__ float g_wtp[(size_t)N_NODES * CAP];          // padded weights
__device__ float4 g_buf0[(size_t)N_NODES * OUT_F / 4];  // fp32 L4 lin
__device__ uint4 g_A[(size_t)N_NODES * H2_F * 2 / 16];  // fp16 activations A
__device__ uint4 g_A2[(size_t)N_NODES * H1_F * 2 / 16]; // fp16 activations B
__device__ uint4 g_Bh[(WT_TOTAL * 2 + 15) / 16];        // fp16 weights (T)

// ===========================================================================
// helpers
// ===========================================================================
__device__ __forceinline__ uint32_t smem_to_u32(const void* p) {
    uint32_t a;
    asm("{ .reg .u64 t; cvta.to.shared.u64 t, %1; cvt.u32.u64 %0, t; }"
        : "=r"(a) : "l"(p));
    return a;
}
__device__ __forceinline__ void cp_async16(uint32_t s, const void* g) {
    asm volatile("cp.async.cg.shared.global [%0], [%1], 16;"
                 :: "r"(s), "l"(__cvta_generic_to_global(g)) : "memory");
}
__device__ __forceinline__ void cp_commit() {
    asm volatile("cp.async.commit_group;" ::: "memory");
}
template <int NN>
__device__ __forceinline__ void cp_wait() {
    asm volatile("cp.async.wait_group %0;" :: "n"(NN) : "memory");
}
__device__ __forceinline__ void mma16816(float* c, const uint32_t* a,
                                         const uint32_t* b) {
    asm volatile(
        "mma.sync.aligned.m16n8k16.row.col.f32.f16.f16.f32 "
        "{%0,%1,%2,%3}, {%4,%5,%6,%7}, {%8,%9}, {%0,%1,%2,%3};"
        : "+f"(c[0]), "+f"(c[1]), "+f"(c[2]), "+f"(c[3])
        : "r"(a[0]), "r"(a[1]), "r"(a[2]), "r"(a[3]), "r"(b[0]), "r"(b[1]));
}
__device__ __forceinline__ void ldmatrix_x4(uint32_t* r, uint32_t saddr) {
    asm volatile("ldmatrix.sync.aligned.m8n8.x4.shared.b16 {%0,%1,%2,%3}, [%4];"
        : "=r"(r[0]), "=r"(r[1]), "=r"(r[2]), "=r"(r[3]) : "r"(saddr));
}
__device__ __forceinline__ void load_edge(const void* ei, int e, int E,
                                          int& s, int& d) {
    if (g_is64) {
        const long long* p = (const long long*)ei;
        s = (int)p[e]; d = (int)p[e + E];
    } else {
        const int* p = (const int*)ei;
        s = p[e]; d = p[e + E];
    }
}

// ===========================================================================
// Setup: zero counters + dtype detect + all-weight transpose, one kernel.
// ===========================================================================
__global__ __launch_bounds__(256)
void k_setup(const void* __restrict__ ei,
             const float* __restrict__ W1, const float* __restrict__ W2,
             const float* __restrict__ W3, const float* __restrict__ W4,
             __half* __restrict__ hi) {
    const int tx = threadIdx.x, ty = threadIdx.y;   // (32, 8)
    const int tid = ty * 32 + tx;
    int b = blockIdx.x;
    if (b < 40) {
        int i = b * 256 + tid;
        if (i < N_NODES) g_cnt[i] = 0;
        if (b == 0) {
            if (tid == 0) g_is64 = 1;
            __syncthreads();
            if (tid < 128) {
                const long long* p = (const long long*)ei;
                long long v = p[tid];
                if (v < 0 || v >= N_NODES) atomicAnd(&g_is64, 0);
            }
        }
        return;
    }
    b -= 40;
    const float* W; int K, N; size_t off;
    if (b < 64)        { W = W1; K = IN_F; N = H1_F; off = W1T_OFF; }
    else if (b < 576)  { b -= 64;   W = W2; K = H1_F; N = H2_F; off = W2T_OFF; }
    else if (b < 1088) { b -= 576;  W = W3; K = H2_F; N = H3_F; off = W3T_OFF; }
    else               { b -= 1088; W = W4; K = H3_F; N = OUT_F; off = W4T_OFF; }
    int KT = K / 32;
    int k0 = (b % KT) * 32, n0 = (b / KT) * 32;

    __shared__ float t[32][33];
#pragma unroll
    for (int j = 0; j < 4; j++)
        t[ty + j * 8][tx] = W[(size_t)(k0 + ty + j * 8) * N + (n0 + tx)];
    __syncthreads();
#pragma unroll
    for (int j = 0; j < 4; j++) {
        float v = t[tx][ty + j * 8];
        int n = n0 + ty + j * 8;
        int k = k0 + tx;
        hi[off + (size_t)n * K + k] = __float2half_rn(v);
    }
}

// ===========================================================================
// CSR (padded-bucket, scan-free)
// ===========================================================================
// One edge pass: count + place simultaneously.
__global__ void k_fill(const void* __restrict__ ei, int E) {
    int e = blockIdx.x * blockDim.x + threadIdx.x;
    if (e >= E) return;
    int s, d;
    load_edge(ei, e, E, s, d);
    int pos = atomicAdd(&g_cnt[d], 1);
    g_colp[(size_t)d * CAP + pos] = s;
}
// dinv = rsqrt(deg + 1)  (elementwise)
__global__ void k_dinv() {
    int i = blockIdx.x * blockDim.x + threadIdx.x;
    if (i < N_NODES) g_dinv[i] = rsqrtf((float)g_cnt[i] + 1.0f);
}
// per-slot weights (warp per node, 8 nodes/block); g_dinv is L1-resident
__global__ __launch_bounds__(256)
void k_wt() {
    int node = blockIdx.x * 8 + threadIdx.y;
    if (node >= N_NODES) return;
    int lane = threadIdx.x;
    int cnt = g_cnt[node];
    float dii = g_dinv[node];
    size_t base = (size_t)node * CAP;
    for (int j = lane; j < cnt; j += 32)
        g_wtp[base + j] = g_dinv[g_colp[base + j]] * dii;
}

// ===========================================================================
// fp16 1-pass GEMM, 128(M)x64(N) CTA tile, 3-stage cp.async pipeline,
// ldmatrix.x4 fragment loads.
// EPI: 0 bias+relu fp32 | 1 bias+relu fp16 | 2 raw fp16 | 3 raw fp32
// NG:  bounds-guard B rows / C cols against Ncols (for Ncols < 64)
// ===========================================================================
#define KC 32
#define SROW 40                        // fp16 row stride (80 B)
#define TILE_A_B (128 * SROW * 2)      // 10240 B
#define TILE_B_B (64 * SROW * 2)       // 5120 B
#define STAGE_B (TILE_A_B + TILE_B_B)  // 15360 B
#define GEMM_SMEM (3 * STAGE_B)        // 46080 B

template <int EPI, bool NG>
__global__ __launch_bounds__(256)
void k_gemm_mma(const uint4* __restrict__ A, const __half* __restrict__ B,
                const float* __restrict__ bias, float* __restrict__ C,
                __half2* __restrict__ Oh,
                int M, int K, int Ncols) {
    extern __shared__ char sm[];
    const uint32_t smb = smem_to_u32(sm);
    const int tid = threadIdx.x;
    const int lane = tid & 31;
    const int wid = tid >> 5;
    const int warp_m = wid & 3;
    const int warp_n = wid >> 2;
    const int g = lane >> 2;
    const int tig = lane & 3;
    const int mrow0 = blockIdx.y * 128;
    const int ncol0 = blockIdx.x * 64;
    const int KU = K >> 3;
    const int nChunks = K / KC;

    uint32_t offA[2], offB[2];
#pragma unroll
    for (int mt = 0; mt < 2; mt++) {
        int row = warp_m * 32 + mt * 16 + (lane & 7) + (lane & 8);
        int kh  = (lane & 16) >> 1;
        offA[mt] = (uint32_t)((row * SROW + kh) * 2);
    }
#pragma unroll
    for (int p = 0; p < 2; p++) {
        int row = warp_n * 32 + p * 16 + (lane & 7) + ((lane & 16) >> 1);
        int kh  = ((lane >> 3) & 1) * 8;
        offB[p] = (uint32_t)(TILE_A_B + (row * SROW + kh) * 2);
    }

    float acc[2][4][4];
#pragma unroll
    for (int i = 0; i < 2; i++)
#pragma unroll
        for (int j = 0; j < 4; j++)
#pragma unroll
            for (int q = 0; q < 4; q++) acc[i][j][q] = 0.0f;

    auto load_chunk = [&](int it, int st) {
        const int ku0 = it * (KC / 8);
        const uint32_t sb = smb + st * STAGE_B;
#pragma unroll
        for (int q = tid; q < 512; q += 256) {
            int row = q >> 2;
            int cb = q & 3;
            uint32_t so = (uint32_t)(row * 80 + cb * 16);
            int gm = mrow0 + row;
            if (gm < M) {
                cp_async16(sb + so, A + (size_t)gm * KU + ku0 + cb);
            } else {
                *(uint4*)(sm + st * STAGE_B + so) = make_uint4(0, 0, 0, 0);
            }
        }
        {
            int q = tid;
            int row = q >> 2;
            int cb = q & 3;
            uint32_t so = (uint32_t)(row * 80 + cb * 16);
            int brow = ncol0 + row;
            if (!NG || brow < Ncols) {
                size_t bb = (size_t)brow * K + it * KC + cb * 8;
                cp_async16(sb + TILE_A_B + so, B + bb);
            } else {
                *(uint4*)(sm + st * STAGE_B + TILE_A_B + so) = make_uint4(0, 0, 0, 0);
            }
        }
        cp_commit();
    };

    load_chunk(0, 0);
    load_chunk(1, 1);
    for (int it = 0; it < nChunks; it++) {
        const int cur = it % 3;
        if (it + 2 < nChunks) {
            load_chunk(it + 2, (it + 2) % 3);
            cp_wait<2>();
        } else if (it + 1 < nChunks) {
            cp_wait<1>();
        } else {
            cp_wait<0>();
        }
        __syncthreads();

        const uint32_t stage = smb + cur * STAGE_B;
#pragma unroll
        for (int ks = 0; ks < KC / 16; ks++) {
            const uint32_t kb = (uint32_t)(ks * 32);
            uint32_t ah[2][4];
            ldmatrix_x4(ah[0], stage + offA[0] + kb);
            ldmatrix_x4(ah[1], stage + offA[1] + kb);
            uint32_t bh[4][2];
            {
                uint32_t r[4];
                ldmatrix_x4(r, stage + offB[0] + kb);
                bh[0][0] = r[0]; bh[0][1] = r[1];
                bh[1][0] = r[2]; bh[1][1] = r[3];
                ldmatrix_x4(r, stage + offB[1] + kb);
                bh[2][0] = r[0]; bh[2][1] = r[1];
                bh[3][0] = r[2]; bh[3][1] = r[3];
            }
#pragma unroll
            for (int mt = 0; mt < 2; mt++)
#pragma unroll
                for (int nt = 0; nt < 4; nt++) mma16816(acc[mt][nt], ah[mt], bh[nt]);
        }
        __syncthreads();
    }

    // Epilogue
#pragma unroll
    for (int mt = 0; mt < 2; mt++) {
        int rbase = mrow0 + warp_m * 32 + mt * 16;
#pragma unroll
        for (int nt = 0; nt < 4; nt++) {
            int col = ncol0 + warp_n * 32 + nt * 8 + tig * 2;
            if (NG && col >= Ncols) continue;
            float b0 = 0.0f, b1 = 0.0f;
            if (EPI == 0 || EPI == 1) { b0 = bias[col]; b1 = bias[col + 1]; }
#pragma unroll
            for (int half = 0; half < 2; half++) {
                int r = rbase + g + half * 8;
                if (r >= M) continue;
                float v0 = acc[mt][nt][half * 2 + 0] + b0;
                float v1 = acc[mt][nt][half * 2 + 1] + b1;
                if (EPI == 0 || EPI == 1) { v0 = fmaxf(v0, 0.0f); v1 = fmaxf(v1, 0.0f); }
                if (EPI == 0 || EPI == 3) {
                    *(float2*)(C + (size_t)r * Ncols + col) = make_float2(v0, v1);
                } else {
                    Oh[((size_t)r * Ncols + col) >> 1] = __floats2half2_rn(v0, v1);
                }
            }
        }
    }
}

// ===========================================================================
// Aggregations — padded buckets (cnt <= 96 fits one 128-wide smem stage)
// ===========================================================================
template <int OUTMODE>
__global__ __launch_bounds__(128)
void k_agg512_h(const uint2* __restrict__ lin,       // fp16 [N,512] as uint2
                const float* __restrict__ bias,
                __half2* __restrict__ outh) {
    const int node = blockIdx.x;
    const int tid = threadIdx.x;
    float dii = g_dinv[node];
    float w0 = dii * dii;

    uint2 sv = lin[(size_t)node * 128 + tid];
    float2 f01 = __half22float2(*(const __half2*)&sv.x);
    float2 f23 = __half22float2(*(const __half2*)&sv.y);
    float a0 = f01.x * w0, a1 = f01.y * w0, a2 = f23.x * w0, a3 = f23.y * w0;

    __shared__ int   s_col[CAP];
    __shared__ float s_w[CAP];
    const int cnt = g_cnt[node];
    const size_t base = (size_t)node * CAP;
    if (tid < cnt) { s_col[tid] = g_colp[base + tid]; s_w[tid] = g_wtp[base + tid]; }
    __syncthreads();
    for (int j = 0; j < cnt; j++) {
        int s = s_col[j];
        float w = s_w[j];
        uint2 v = lin[(size_t)s * 128 + tid];
        float2 g01 = __half22float2(*(const __half2*)&v.x);
        float2 g23 = __half22float2(*(const __half2*)&v.y);
        a0 = fmaf(w, g01.x, a0); a1 = fmaf(w, g01.y, a1);
        a2 = fmaf(w, g23.x, a2); a3 = fmaf(w, g23.y, a3);
    }
    if (OUTMODE == 2) {
        float4 b = reinterpret_cast<const float4*>(bias)[tid];
        a0 = fmaxf(a0 + b.x, 0.0f); a1 = fmaxf(a1 + b.y, 0.0f);
        a2 = fmaxf(a2 + b.z, 0.0f); a3 = fmaxf(a3 + b.w, 0.0f);
    }
    size_t o = (size_t)node * 256 + tid * 2;
    outh[o]     = __floats2half2_rn(a0, a1);
    outh[o + 1] = __floats2half2_rn(a2, a3);
}

// x [N,128] fp32 -> fp16 with aggregation; warp per node, 8 nodes/block
__global__ __launch_bounds__(256)
void k_agg128h(const float4* __restrict__ lin, __half2* __restrict__ oh) {
    int node = blockIdx.x * 8 + threadIdx.y;
    if (node >= N_NODES) return;
    int lane = threadIdx.x;
    float dii = g_dinv[node];
    float w0 = dii * dii;
    float4 a = lin[(size_t)node * 32 + lane];
    a.x *= w0; a.y *= w0; a.z *= w0; a.w *= w0;
    int cnt = g_cnt[node];
    size_t base = (size_t)node * CAP;
    for (int j = 0; j < cnt; j++) {
        int s = g_colp[base + j];
        float w = g_wtp[base + j];
        float4 v = lin[(size_t)s * 32 + lane];
        a.x = fmaf(w, v.x, a.x); a.y = fmaf(w, v.y, a.y);
        a.z = fmaf(w, v.z, a.z); a.w = fmaf(w, v.w, a.w);
    }
    size_t o = (size_t)node * 64 + lane * 2;
    oh[o]     = __floats2half2_rn(a.x, a.y);
    oh[o + 1] = __floats2half2_rn(a.z, a.w);
}

// L4 final: aggregate (H=32, fp32 lin) + bias + log_softmax; warp per node
__global__ __launch_bounds__(256)
void k_agg_softmax32(const float* __restrict__ lin,
                     const float* __restrict__ bias,
                     float* __restrict__ out) {
    int node = blockIdx.x * 8 + threadIdx.y;
    if (node >= N_NODES) return;
    int lane = threadIdx.x;
    float dii = g_dinv[node];
    float v = lin[(size_t)node * 32 + lane] * dii * dii;
    int cnt = g_cnt[node];
    size_t base = (size_t)node * CAP;
    for (int j = 0; j < cnt; j++) {
        int s = g_colp[base + j];
        float w = g_wtp[base + j];
        v = fmaf(w, lin[(size_t)s * 32 + lane], v);
    }
    v += bias[lane];
    float m = v;
#pragma unroll
    for (int o = 16; o > 0; o >>= 1)
        m = fmaxf(m, __shfl_xor_sync(0xFFFFFFFFu, m, o));
    float ex = expf(v - m);
    float s = ex;
#pragma unroll
    for (int o = 16; o > 0; o >>= 1)
        s += __shfl_xor_sync(0xFFFFFFFFu, s, o);
    out[(size_t)node * 32 + lane] = v - m - logf(s);
}

// ===========================================================================
// Launch
// ===========================================================================
static inline int cdiv(long long a, int b) { return (int)((a + b - 1) / b); }

extern "C" void kernel_launch(void* const* d_in, const int* in_sizes, int n_in,
                              void* d_out, int out_size) {
    const float* x  = (const float*)d_in[0];
    const void*  ei = d_in[1];
    const float* W1 = (const float*)d_in[2];
    const float* b1 = (const float*)d_in[3];
    const float* W2 = (const float*)d_in[4];
    const float* b2 = (const float*)d_in[5];
    const float* W3 = (const float*)d_in[6];
    const float* b3 = (const float*)d_in[7];
    const float* W4 = (const float*)d_in[8];
    const float* b4 = (const float*)d_in[9];
    float* out = (float*)d_out;

    const int E = in_sizes[1] / 2;

    float4 *buf0;
    uint4 *A, *A2, *Bh;
    cudaGetSymbolAddress((void**)&buf0, g_buf0);
    cudaGetSymbolAddress((void**)&A, g_A);
    cudaGetSymbolAddress((void**)&A2, g_A2);
    cudaGetSymbolAddress((void**)&Bh, g_Bh);

    cudaFuncSetAttribute((const void*)k_gemm_mma<1, false>,
                         cudaFuncAttributeMaxDynamicSharedMemorySize, GEMM_SMEM);
    cudaFuncSetAttribute((const void*)k_gemm_mma<2, false>,
                         cudaFuncAttributeMaxDynamicSharedMemorySize, GEMM_SMEM);
    cudaFuncSetAttribute((const void*)k_gemm_mma<3, true>,
                         cudaFuncAttributeMaxDynamicSharedMemorySize, GEMM_SMEM);

    const int MT = cdiv(N_NODES, 128);
    const __half* BW = (const __half*)Bh;

    // --- setup (zero+detect+weights) + scan-free CSR ---
    k_setup<<<1144, dim3(32, 8)>>>(ei, W1, W2, W3, W4, (__half*)Bh);
    k_fill<<<cdiv(E, 256), 256>>>(ei, E);
    k_dinv<<<cdiv(N_NODES, 256), 256>>>();
    k_wt<<<cdiv(N_NODES, 8), dim3(32, 8)>>>();

    // --- L1: agg(x)->fp16 (A2) -> GEMM K=128 N=512 bias+relu -> fp16 h1 (A) ---
    k_agg128h<<<cdiv(N_NODES, 8), dim3(32, 8)>>>((const float4*)x, (__half2*)A2);
    k_gemm_mma<1, false><<<dim3(H1_F / 64, MT), 256, GEMM_SMEM>>>(
        A2, BW + W1T_OFF, b1, nullptr, (__half2*)A, N_NODES, IN_F, H1_F);

    // --- L2: agg(h1)->fp16 (A2) -> GEMM K=512 N=1024 bias+relu -> fp16 h2 (A) ---
    k_agg512_h<0><<<N_NODES, 128>>>((const uint2*)A, nullptr, (__half2*)A2);
    k_gemm_mma<1, false><<<dim3(H2_F / 64, MT), 256, GEMM_SMEM>>>(
        A2, BW + W2T_OFF, b2, nullptr, (__half2*)A, N_NODES, H1_F, H2_F);

    // --- L3: GEMM K=1024 N=512 raw fp16 (A2) -> agg+bias+relu -> fp16 h3 (A) ---
    k_gemm_mma<2, false><<<dim3(H3_F / 64, MT), 256, GEMM_SMEM>>>(
        A, BW + W3T_OFF, nullptr, nullptr, (__half2*)A2, N_NODES, H2_F, H3_F);
    k_agg512_h<2><<<N_NODES, 128>>>((const uint2*)A2, b3, (__half2*)A);

    // --- L4: fp16 MMA GEMM K=512 N=32 raw fp32 -> buf0 ; agg+bias+softmax ---
    k_gemm_mma<3, true><<<dim3(1, MT), 256, GEMM_SMEM>>>(
        A, BW + W4T_OFF, nullptr, (float*)buf0, nullptr, N_NODES, H3_F, OUT_F);
    k_agg_softmax32<<<cdiv(N_NODES, 8), dim3(32, 8)>>>(
        (const float*)buf0, b4, out);
}

// round 17
// speedup vs baseline: 1.2422x; 1.0194x over previous
#include <cuda_runtime.h>
#include <cuda_fp16.h>
#include <math.h>
#include <stdint.h>

#define N_NODES 10000
#define E_EDGES 160000
#define IN_F    128
#define H1_F    512
#define H2_F    1024
#define H3_F    512
#define OUT_F   32
#define CAP     96          // padded CSR bucket capacity (P(deg>=96) ~ 1e-43)

// Weight-transpose buffer offsets (fp16 elements)
#define W1T_OFF 0
#define W2T_OFF (IN_F * H1_F)
#define W3T_OFF (W2T_OFF + H1_F * H2_F)
#define W4T_OFF (W3T_OFF + H2_F * H3_F)
#define WT_TOTAL (W4T_OFF + H3_F * OUT_F)

// ===========================================================================
// Scratch (static device globals)
// ===========================================================================
__device__ int   g_is64;
__device__ int   g_cnt[N_NODES];
__device__ int   g_colp[(size_t)N_NODES * CAP];         // padded col buckets
__device__ float g_wtp[(size_t)N_NODES * CAP];          // padded weights
__device__ float4 g_buf0[(size_t)N_NODES * OUT_F / 4];  // fp32 L4 lin
__device__ uint4 g_A[(size_t)N_NODES * H2_F * 2 / 16];  // fp16 activations A
__device__ uint4 g_A2[(size_t)N_NODES * H1_F * 2 / 16]; // fp16 activations B
__device__ uint4 g_Bh[(WT_TOTAL * 2 + 15) / 16];        // fp16 weights (T)

// ===========================================================================
// helpers
// ===========================================================================
__device__ __forceinline__ uint32_t smem_to_u32(const void* p) {
    uint32_t a;
    asm("{ .reg .u64 t; cvta.to.shared.u64 t, %1; cvt.u32.u64 %0, t; }"
        : "=r"(a) : "l"(p));
    return a;
}
__device__ __forceinline__ void cp_async16(uint32_t s, const void* g) {
    asm volatile("cp.async.cg.shared.global [%0], [%1], 16;"
                 :: "r"(s), "l"(__cvta_generic_to_global(g)) : "memory");
}
__device__ __forceinline__ void cp_commit() {
    asm volatile("cp.async.commit_group;" ::: "memory");
}
template <int NN>
__device__ __forceinline__ void cp_wait() {
    asm volatile("cp.async.wait_group %0;" :: "n"(NN) : "memory");
}
__device__ __forceinline__ void mma16816(float* c, const uint32_t* a,
                                         const uint32_t* b) {
    asm volatile(
        "mma.sync.aligned.m16n8k16.row.col.f32.f16.f16.f32 "
        "{%0,%1,%2,%3}, {%4,%5,%6,%7}, {%8,%9}, {%0,%1,%2,%3};"
        : "+f"(c[0]), "+f"(c[1]), "+f"(c[2]), "+f"(c[3])
        : "r"(a[0]), "r"(a[1]), "r"(a[2]), "r"(a[3]), "r"(b[0]), "r"(b[1]));
}
__device__ __forceinline__ void ldmatrix_x4(uint32_t* r, uint32_t saddr) {
    asm volatile("ldmatrix.sync.aligned.m8n8.x4.shared.b16 {%0,%1,%2,%3}, [%4];"
        : "=r"(r[0]), "=r"(r[1]), "=r"(r[2]), "=r"(r[3]) : "r"(saddr));
}
__device__ __forceinline__ void load_edge(const void* ei, int e, int E,
                                          int& s, int& d) {
    if (g_is64) {
        const long long* p = (const long long*)ei;
        s = (int)p[e]; d = (int)p[e + E];
    } else {
        const int* p = (const int*)ei;
        s = p[e]; d = p[e + E];
    }
}

// ===========================================================================
// Setup: zero counters + dtype detect + all-weight transpose, one kernel.
// ===========================================================================
__global__ __launch_bounds__(256)
void k_setup(const void* __restrict__ ei,
             const float* __restrict__ W1, const float* __restrict__ W2,
             const float* __restrict__ W3, const float* __restrict__ W4,
             __half* __restrict__ hi) {
    const int tx = threadIdx.x, ty = threadIdx.y;   // (32, 8)
    const int tid = ty * 32 + tx;
    int b = blockIdx.x;
    if (b < 40) {
        int i = b * 256 + tid;
        if (i < N_NODES) g_cnt[i] = 0;
        if (b == 0) {
            if (tid == 0) g_is64 = 1;
            __syncthreads();
            if (tid < 128) {
                const long long* p = (const long long*)ei;
                long long v = p[tid];
                if (v < 0 || v >= N_NODES) atomicAnd(&g_is64, 0);
            }
        }
        return;
    }
    b -= 40;
    const float* W; int K, N; size_t off;
    if (b < 64)        { W = W1; K = IN_F; N = H1_F; off = W1T_OFF; }
    else if (b < 576)  { b -= 64;   W = W2; K = H1_F; N = H2_F; off = W2T_OFF; }
    else if (b < 1088) { b -= 576;  W = W3; K = H2_F; N = H3_F; off = W3T_OFF; }
    else               { b -= 1088; W = W4; K = H3_F; N = OUT_F; off = W4T_OFF; }
    int KT = K / 32;
    int k0 = (b % KT) * 32, n0 = (b / KT) * 32;

    __shared__ float t[32][33];
#pragma unroll
    for (int j = 0; j < 4; j++)
        t[ty + j * 8][tx] = W[(size_t)(k0 + ty + j * 8) * N + (n0 + tx)];
    __syncthreads();
#pragma unroll
    for (int j = 0; j < 4; j++) {
        float v = t[tx][ty + j * 8];
        int n = n0 + ty + j * 8;
        int k = k0 + tx;
        hi[off + (size_t)n * K + k] = __float2half_rn(v);
    }
}

// ===========================================================================
// CSR (padded-bucket, scan-free): one edge pass, count + place.
// ===========================================================================
__global__ void k_fill(const void* __restrict__ ei, int E) {
    int e = blockIdx.x * blockDim.x + threadIdx.x;
    if (e >= E) return;
    int s, d;
    load_edge(ei, e, E, s, d);
    int pos = atomicAdd(&g_cnt[d], 1);
    g_colp[(size_t)d * CAP + pos] = s;
}

// ===========================================================================
// Fused: per-edge weights (written to g_wtp for later layers) + L1
// pre-aggregation of x [N,128] -> fp16. Warp per node, 8 nodes/block.
// Weight math rides in the staging phase, off the per-edge critical path.
// ===========================================================================
__global__ __launch_bounds__(256)
void k_agg128wt(const float4* __restrict__ lin, __half2* __restrict__ oh) {
    __shared__ int   s_col[8][CAP];
    __shared__ float s_w[8][CAP];
    int node = blockIdx.x * 8 + threadIdx.y;
    if (node >= N_NODES) return;
    const int ty = threadIdx.y;
    const int lane = threadIdx.x;
    const int cnt = g_cnt[node];
    const float dii = rsqrtf((float)cnt + 1.0f);
    const size_t base = (size_t)node * CAP;

    // staging: cols + weights (parallel across lanes; <=3 rounds)
    for (int j = lane; j < cnt; j += 32) {
        int c = g_colp[base + j];
        float w = rsqrtf((float)g_cnt[c] + 1.0f) * dii;
        s_col[ty][j] = c;
        s_w[ty][j] = w;
        g_wtp[base + j] = w;
    }
    __syncwarp();

    float w0 = dii * dii;
    float4 a = lin[(size_t)node * 32 + lane];
    a.x *= w0; a.y *= w0; a.z *= w0; a.w *= w0;
    for (int j = 0; j < cnt; j++) {
        int s = s_col[ty][j];
        float w = s_w[ty][j];
        float4 v = lin[(size_t)s * 32 + lane];
        a.x = fmaf(w, v.x, a.x); a.y = fmaf(w, v.y, a.y);
        a.z = fmaf(w, v.z, a.z); a.w = fmaf(w, v.w, a.w);
    }
    size_t o = (size_t)node * 64 + lane * 2;
    oh[o]     = __floats2half2_rn(a.x, a.y);
    oh[o + 1] = __floats2half2_rn(a.z, a.w);
}

// ===========================================================================
// fp16 1-pass GEMM, 128(M)x64(N) CTA tile, 3-stage cp.async pipeline,
// ldmatrix.x4 fragment loads.
// EPI: 0 bias+relu fp32 | 1 bias+relu fp16 | 2 raw fp16 | 3 raw fp32
// NG:  bounds-guard B rows / C cols against Ncols (for Ncols < 64)
// ===========================================================================
#define KC 32
#define SROW 40                        // fp16 row stride (80 B)
#define TILE_A_B (128 * SROW * 2)      // 10240 B
#define TILE_B_B (64 * SROW * 2)       // 5120 B
#define STAGE_B (TILE_A_B + TILE_B_B)  // 15360 B
#define GEMM_SMEM (3 * STAGE_B)        // 46080 B

template <int EPI, bool NG>
__global__ __launch_bounds__(256)
void k_gemm_mma(const uint4* __restrict__ A, const __half* __restrict__ B,
                const float* __restrict__ bias, float* __restrict__ C,
                __half2* __restrict__ Oh,
                int M, int K, int Ncols) {
    extern __shared__ char sm[];
    const uint32_t smb = smem_to_u32(sm);
    const int tid = threadIdx.x;
    const int lane = tid & 31;
    const int wid = tid >> 5;
    const int warp_m = wid & 3;
    const int warp_n = wid >> 2;
    const int g = lane >> 2;
    const int tig = lane & 3;
    const int mrow0 = blockIdx.y * 128;
    const int ncol0 = blockIdx.x * 64;
    const int KU = K >> 3;
    const int nChunks = K / KC;

    uint32_t offA[2], offB[2];
#pragma unroll
    for (int mt = 0; mt < 2; mt++) {
        int row = warp_m * 32 + mt * 16 + (lane & 7) + (lane & 8);
        int kh  = (lane & 16) >> 1;
        offA[mt] = (uint32_t)((row * SROW + kh) * 2);
    }
#pragma unroll
    for (int p = 0; p < 2; p++) {
        int row = warp_n * 32 + p * 16 + (lane & 7) + ((lane & 16) >> 1);
        int kh  = ((lane >> 3) & 1) * 8;
        offB[p] = (uint32_t)(TILE_A_B + (row * SROW + kh) * 2);
    }

    float acc[2][4][4];
#pragma unroll
    for (int i = 0; i < 2; i++)
#pragma unroll
        for (int j = 0; j < 4; j++)
#pragma unroll
            for (int q = 0; q < 4; q++) acc[i][j][q] = 0.0f;

    auto load_chunk = [&](int it, int st) {
        const int ku0 = it * (KC / 8);
        const uint32_t sb = smb + st * STAGE_B;
#pragma unroll
        for (int q = tid; q < 512; q += 256) {
            int row = q >> 2;
            int cb = q & 3;
            uint32_t so = (uint32_t)(row * 80 + cb * 16);
            int gm = mrow0 + row;
            if (gm < M) {
                cp_async16(sb + so, A + (size_t)gm * KU + ku0 + cb);
            } else {
                *(uint4*)(sm + st * STAGE_B + so) = make_uint4(0, 0, 0, 0);
            }
        }
        {
            int q = tid;
            int row = q >> 2;
            int cb = q & 3;
            uint32_t so = (uint32_t)(row * 80 + cb * 16);
            int brow = ncol0 + row;
            if (!NG || brow < Ncols) {
                size_t bb = (size_t)brow * K + it * KC + cb * 8;
                cp_async16(sb + TILE_A_B + so, B + bb);
            } else {
                *(uint4*)(sm + st * STAGE_B + TILE_A_B + so) = make_uint4(0, 0, 0, 0);
            }
        }
        cp_commit();
    };

    load_chunk(0, 0);
    load_chunk(1, 1);
    for (int it = 0; it < nChunks; it++) {
        const int cur = it % 3;
        if (it + 2 < nChunks) {
            load_chunk(it + 2, (it + 2) % 3);
            cp_wait<2>();
        } else if (it + 1 < nChunks) {
            cp_wait<1>();
        } else {
            cp_wait<0>();
        }
        __syncthreads();

        const uint32_t stage = smb + cur * STAGE_B;
#pragma unroll
        for (int ks = 0; ks < KC / 16; ks++) {
            const uint32_t kb = (uint32_t)(ks * 32);
            uint32_t ah[2][4];
            ldmatrix_x4(ah[0], stage + offA[0] + kb);
            ldmatrix_x4(ah[1], stage + offA[1] + kb);
            uint32_t bh[4][2];
            {
                uint32_t r[4];
                ldmatrix_x4(r, stage + offB[0] + kb);
                bh[0][0] = r[0]; bh[0][1] = r[1];
                bh[1][0] = r[2]; bh[1][1] = r[3];
                ldmatrix_x4(r, stage + offB[1] + kb);
                bh[2][0] = r[0]; bh[2][1] = r[1];
                bh[3][0] = r[2]; bh[3][1] = r[3];
            }
#pragma unroll
            for (int mt = 0; mt < 2; mt++)
#pragma unroll
                for (int nt = 0; nt < 4; nt++) mma16816(acc[mt][nt], ah[mt], bh[nt]);
        }
        __syncthreads();
    }

    // Epilogue
#pragma unroll
    for (int mt = 0; mt < 2; mt++) {
        int rbase = mrow0 + warp_m * 32 + mt * 16;
#pragma unroll
        for (int nt = 0; nt < 4; nt++) {
            int col = ncol0 + warp_n * 32 + nt * 8 + tig * 2;
            if (NG && col >= Ncols) continue;
            float b0 = 0.0f, b1 = 0.0f;
            if (EPI == 0 || EPI == 1) { b0 = bias[col]; b1 = bias[col + 1]; }
#pragma unroll
            for (int half = 0; half < 2; half++) {
                int r = rbase + g + half * 8;
                if (r >= M) continue;
                float v0 = acc[mt][nt][half * 2 + 0] + b0;
                float v1 = acc[mt][nt][half * 2 + 1] + b1;
                if (EPI == 0 || EPI == 1) { v0 = fmaxf(v0, 0.0f); v1 = fmaxf(v1, 0.0f); }
                if (EPI == 0 || EPI == 3) {
                    *(float2*)(C + (size_t)r * Ncols + col) = make_float2(v0, v1);
                } else {
                    Oh[((size_t)r * Ncols + col) >> 1] = __floats2half2_rn(v0, v1);
                }
            }
        }
    }
}

// ===========================================================================
// Aggregations — padded buckets (cnt <= 96 fits one 128-wide smem stage)
// ===========================================================================
template <int OUTMODE>
__global__ __launch_bounds__(128)
void k_agg512_h(const uint2* __restrict__ lin,       // fp16 [N,512] as uint2
                const float* __restrict__ bias,
                __half2* __restrict__ outh) {
    const int node = blockIdx.x;
    const int tid = threadIdx.x;
    const int cnt = g_cnt[node];
    float dii = rsqrtf((float)cnt + 1.0f);
    float w0 = dii * dii;

    uint2 sv = lin[(size_t)node * 128 + tid];
    float2 f01 = __half22float2(*(const __half2*)&sv.x);
    float2 f23 = __half22float2(*(const __half2*)&sv.y);
    float a0 = f01.x * w0, a1 = f01.y * w0, a2 = f23.x * w0, a3 = f23.y * w0;

    __shared__ int   s_col[CAP];
    __shared__ float s_w[CAP];
    const size_t base = (size_t)node * CAP;
    if (tid < cnt) { s_col[tid] = g_colp[base + tid]; s_w[tid] = g_wtp[base + tid]; }
    __syncthreads();
    for (int j = 0; j < cnt; j++) {
        int s = s_col[j];
        float w = s_w[j];
        uint2 v = lin[(size_t)s * 128 + tid];
        float2 g01 = __half22float2(*(const __half2*)&v.x);
        float2 g23 = __half22float2(*(const __half2*)&v.y);
        a0 = fmaf(w, g01.x, a0); a1 = fmaf(w, g01.y, a1);
        a2 = fmaf(w, g23.x, a2); a3 = fmaf(w, g23.y, a3);
    }
    if (OUTMODE == 2) {
        float4 b = reinterpret_cast<const float4*>(bias)[tid];
        a0 = fmaxf(a0 + b.x, 0.0f); a1 = fmaxf(a1 + b.y, 0.0f);
        a2 = fmaxf(a2 + b.z, 0.0f); a3 = fmaxf(a3 + b.w, 0.0f);
    }
    size_t o = (size_t)node * 256 + tid * 2;
    outh[o]     = __floats2half2_rn(a0, a1);
    outh[o + 1] = __floats2half2_rn(a2, a3);
}

// L4 final: aggregate (H=32, fp32 lin) + bias + log_softmax; warp per node
__global__ __launch_bounds__(256)
void k_agg_softmax32(const float* __restrict__ lin,
                     const float* __restrict__ bias,
                     float* __restrict__ out) {
    int node = blockIdx.x * 8 + threadIdx.y;
    if (node >= N_NODES) return;
    int lane = threadIdx.x;
    const int cnt = g_cnt[node];
    float dii = rsqrtf((float)cnt + 1.0f);
    float v = lin[(size_t)node * 32 + lane] * dii * dii;
    size_t base = (size_t)node * CAP;
    for (int j = 0; j < cnt; j++) {
        int s = g_colp[base + j];
        float w = g_wtp[base + j];
        v = fmaf(w, lin[(size_t)s * 32 + lane], v);
    }
    v += bias[lane];
    float m = v;
#pragma unroll
    for (int o = 16; o > 0; o >>= 1)
        m = fmaxf(m, __shfl_xor_sync(0xFFFFFFFFu, m, o));
    float ex = expf(v - m);
    float s = ex;
#pragma unroll
    for (int o = 16; o > 0; o >>= 1)
        s += __shfl_xor_sync(0xFFFFFFFFu, s, o);
    out[(size_t)node * 32 + lane] = v - m - logf(s);
}

// ===========================================================================
// Launch
// ===========================================================================
static inline int cdiv(long long a, int b) { return (int)((a + b - 1) / b); }

extern "C" void kernel_launch(void* const* d_in, const int* in_sizes, int n_in,
                              void* d_out, int out_size) {
    const float* x  = (const float*)d_in[0];
    const void*  ei = d_in[1];
    const float* W1 = (const float*)d_in[2];
    const float* b1 = (const float*)d_in[3];
    const float* W2 = (const float*)d_in[4];
    const float* b2 = (const float*)d_in[5];
    const float* W3 = (const float*)d_in[6];
    const float* b3 = (const float*)d_in[7];
    const float* W4 = (const float*)d_in[8];
    const float* b4 = (const float*)d_in[9];
    float* out = (float*)d_out;

    const int E = in_sizes[1] / 2;

    float4 *buf0;
    uint4 *A, *A2, *Bh;
    cudaGetSymbolAddress((void**)&buf0, g_buf0);
    cudaGetSymbolAddress((void**)&A, g_A);
    cudaGetSymbolAddress((void**)&A2, g_A2);
    cudaGetSymbolAddress((void**)&Bh, g_Bh);

    cudaFuncSetAttribute((const void*)k_gemm_mma<1, false>,
                         cudaFuncAttributeMaxDynamicSharedMemorySize, GEMM_SMEM);
    cudaFuncSetAttribute((const void*)k_gemm_mma<2, false>,
                         cudaFuncAttributeMaxDynamicSharedMemorySize, GEMM_SMEM);
    cudaFuncSetAttribute((const void*)k_gemm_mma<3, true>,
                         cudaFuncAttributeMaxDynamicSharedMemorySize, GEMM_SMEM);

    const int MT = cdiv(N_NODES, 128);
    const __half* BW = (const __half*)Bh;

    // --- setup (zero+detect+weights) + scan-free CSR ---
    k_setup<<<1144, dim3(32, 8)>>>(ei, W1, W2, W3, W4, (__half*)Bh);
    k_fill<<<cdiv(E, 256), 256>>>(ei, E);

    // --- L1: fused weights + agg(x)->fp16 (A2) -> GEMM -> fp16 h1 (A) ---
    k_agg128wt<<<cdiv(N_NODES, 8), dim3(32, 8)>>>((const float4*)x, (__half2*)A2);
    k_gemm_mma<1, false><<<dim3(H1_F / 64, MT), 256, GEMM_SMEM>>>(
        A2, BW + W1T_OFF, b1, nullptr, (__half2*)A, N_NODES, IN_F, H1_F);

    // --- L2: agg(h1)->fp16 (A2) -> GEMM K=512 N=1024 bias+relu -> fp16 h2 (A) ---
    k_agg512_h<0><<<N_NODES, 128>>>((const uint2*)A, nullptr, (__half2*)A2);
    k_gemm_mma<1, false><<<dim3(H2_F / 64, MT), 256, GEMM_SMEM>>>(
        A2, BW + W2T_OFF, b2, nullptr, (__half2*)A, N_NODES, H1_F, H2_F);

    // --- L3: GEMM K=1024 N=512 raw fp16 (A2) -> agg+bias+relu -> fp16 h3 (A) ---
    k_gemm_mma<2, false><<<dim3(H3_F / 64, MT), 256, GEMM_SMEM>>>(
        A, BW + W3T_OFF, nullptr, nullptr, (__half2*)A2, N_NODES, H2_F, H3_F);
    k_agg512_h<2><<<N_NODES, 128>>>((const uint2*)A2, b3, (__half2*)A);

    // --- L4: fp16 MMA GEMM K=512 N=32 raw fp32 -> buf0 ; agg+bias+softmax ---
    k_gemm_mma<3, true><<<dim3(1, MT), 256, GEMM_SMEM>>>(
        A, BW + W4T_OFF, nullptr, (float*)buf0, nullptr, N_NODES, H3_F, OUT_F);
    k_agg_softmax32<<<cdiv(N_NODES, 8), dim3(32, 8)>>>(
        (const float*)buf0, b4, out);
}